// round 15
// baseline (speedup 1.0000x reference)
#include <cuda_runtime.h>
#include <cuda_fp16.h>
#include <math.h>
#include <stdint.h>

#define B_    2
#define T_    1024
#define BT_   2048
#define DIM_  2048
#define NH_   16
#define DH_   128
#define DRH_  64
#define DC_   512
#define NE_   16
#define TOPK_ 4
#define MOE_  1024
#define MOESH_ 2048
#define CAP_  2048
#define QKD_  192
#define NCDQ_ 1088
#define SC_   256.0f
#define ASC_  (1.0f/65536.0f)

// ---------------- scratch ----------------
__device__ float g_S  [(size_t)B_*NH_*T_*T_];
__device__ float g_V  [BT_*NH_*DH_];
__device__ float g_x1 [BT_*DIM_];
__device__ float g_xn [BT_*DIM_];
__device__ float g_pk [2][(size_t)BT_*NCDQ_];
__device__ int   g_cnt[NE_];
__device__ int   g_tok[NE_*CAP_];
__device__ float g_wt [NE_*CAP_];
// fp16 pair-split buffers (uint2 = (hi2,lo2) of k,k+1), values x*256
__device__ __align__(16) uint2 g_h2  [BT_*DIM_/2];
__device__ __align__(16) uint2 g_cdq2[(size_t)BT_*NCDQ_/2];
__device__ __align__(16) uint2 g_Q2  [BT_*NH_*QKD_/2];
__device__ __align__(16) uint2 g_K2  [BT_*NH_*QKD_/2];
__device__ __align__(16) uint2 g_O2  [BT_*NH_*DH_/2];
__device__ __align__(16) uint2 g_Wo2 [(size_t)DIM_*NH_*DH_/2];
__device__ __align__(16) uint2 g_xn2 [BT_*DIM_/2];
// fp16 plane buffers (hi plane then lo plane)
__device__ __align__(16) __half g_a1P [(size_t)2*BT_*MOESH_];
__device__ __align__(16) __half g_h1P [(size_t)2*NE_*CAP_*MOE_];
// split weights
__device__ __align__(16) uint2 g_wA2  [(size_t)NCDQ_*DIM_/2];
__device__ __align__(16) uint2 g_wuk2 [DH_*NH_*DC_/2];
__device__ __align__(16) uint2 g_wuv2 [DH_*NH_*DC_/2];
__device__ __align__(16) uint2 g_wuq2 [DH_*NH_*DC_/2];
__device__ __align__(16) uint2 g_wqr2 [DRH_*NH_*DC_/2];
__device__ __align__(16) uint2 g_w13s2[(size_t)(DIM_/2)*2*MOESH_];
__device__ __align__(16) uint2 g_w2s2 [(size_t)(MOESH_/2)*DIM_];
__device__ __align__(16) uint2 g_w13r2[(size_t)NE_*(DIM_/2)*2*MOE_];
__device__ __align__(16) uint2 g_w2r2 [(size_t)NE_*(MOE_/2)*DIM_];

__device__ __forceinline__ uint2 split2(float x, float y) {
    __half hx = __float2half_rn(x), hy = __float2half_rn(y);
    float lx = x - __half2float(hx), ly = y - __half2float(hy);
    __half2 h = __halves2half2(hx, hy);
    __half2 l = __halves2half2(__float2half_rn(lx), __float2half_rn(ly));
    uint2 r; r.x = *(uint32_t*)&h; r.y = *(uint32_t*)&l;
    return r;
}
__device__ __forceinline__ void mma_f16(float* c, const uint32_t* a, const uint32_t* b) {
    asm volatile("mma.sync.aligned.m16n8k16.row.col.f32.f16.f16.f32 "
        "{%0,%1,%2,%3}, {%4,%5,%6,%7}, {%8,%9}, {%0,%1,%2,%3};\n"
        : "+f"(c[0]), "+f"(c[1]), "+f"(c[2]), "+f"(c[3])
        : "r"(a[0]), "r"(a[1]), "r"(a[2]), "r"(a[3]), "r"(b[0]), "r"(b[1]));
}

struct GemmP {
    const void* A; const void* B; void* C; const float* res;
    int M, N, K, lda, ldb, ldc;
    long long aLo;           // APL: lo-plane offset in ELEMENTS
    float alpha;
    long long aO1, aO2, bO1, bO2, cO1, cO2;  // APL: aO in ELEMENTS
    int zdiv, cap;
    const int* Mvec; const int* aRows; const int* cRows; const float* wRow;
    int causal, causalAV, outSplit, siluPair;
    long long cLoP;          // siluPair: lo plane offset (elements) of C
};

// ============ cp.async GEMM (pair-split operands) ==============================
// MODE 0: B NN pair-packed [K/2][N]; MODE 1: B NT [N][K/2].
// APL=0: A pair-packed [M][K/2] uint2.  APL=1: A = half planes (hi @A, lo @A+aLo).
#define CA_STAGE_U2 2112
#define CA_SMEM_BYTES (4 * CA_STAGE_U2 * 8)

__device__ __forceinline__ void cp_async8(uint32_t saddr, const void* gaddr, int sz) {
    asm volatile("cp.async.ca.shared.global [%0], [%1], 8, %2;"
                 :: "r"(saddr), "l"(gaddr), "r"(sz) : "memory");
}
__device__ __forceinline__ void cp_async4(uint32_t saddr, const void* gaddr, int sz) {
    asm volatile("cp.async.ca.shared.global [%0], [%1], 4, %2;"
                 :: "r"(saddr), "l"(gaddr), "r"(sz) : "memory");
}

template<int MODE, int APL>
__global__ __launch_bounds__(256, 2) void gemm_ca(GemmP p) {
    extern __shared__ uint2 dyn[];
    uint32_t smemBase = (uint32_t)__cvta_generic_to_shared(dyn);

    int z = blockIdx.z, z1 = z / p.zdiv, z2 = z - z1 * p.zdiv;
    long long zA = z1 * p.aO1 + z2 * p.aO2;
    long long zB = z1 * p.bO1 + z2 * p.bO2;
    long long zC = z1 * p.cO1 + z2 * p.cO2;
    int M = p.Mvec ? p.Mvec[z] : p.M;
    int m0 = blockIdx.y * 128, n0 = blockIdx.x * 128;
    if (m0 >= M) return;
    if (MODE == 1 && p.causal && n0 >= m0 + 128) return;
    int tid = threadIdx.x, lane = tid & 31, warp = tid >> 5;
    int wm = (warp & 1) << 6, wn = (warp >> 1) << 5;
    int gid = lane >> 2, tg = lane & 3;

    long long gA[4]; uint32_t sAoff[4]; int szA[4];
    long long gB[4]; uint32_t sBoff[4]; int szB[4];
    long long strideB = (MODE == 1) ? 8 : (long long)8 * p.ldb;
#pragma unroll
    for (int i = 0; i < 4; i++) {
        int e = tid + 256 * i;
        int am = e >> 3, ak = e & 7;
        int row = m0 + am;
        bool va = row < M;
        long long ar = 0;
        if (va) ar = p.aRows ? (long long)p.aRows[(long long)z * p.cap + row]
                             : (long long)row;
        if (APL) gA[i] = (zA + ar * p.lda) / 2 + ak;   // uint32 index into hi plane
        else     gA[i] = zA + ar * p.lda + ak;         // uint2 pair index
        sAoff[i] = (uint32_t)(ak * 132 + am) * 8;
        szA[i] = va ? 8 : 0;
        if (MODE == 1) {
            int bn = e >> 3, bk = e & 7;
            bool vb = (n0 + bn) < p.N;
            gB[i] = zB + (long long)(vb ? (n0 + bn) : 0) * p.ldb + bk;
            sBoff[i] = (uint32_t)(1056 + bk * 132 + bn) * 8;
            szB[i] = vb ? 8 : 0;
        } else {
            int bk = e >> 7, bn = e & 127;
            bool vb = (n0 + bn) < p.N;
            gB[i] = zB + (long long)bk * p.ldb + n0 + (vb ? bn : 0);
            sBoff[i] = (uint32_t)(1056 + bk * 132 + bn) * 8;
            szB[i] = vb ? 8 : 0;
        }
    }

    float acc[4][4][4];
#pragma unroll
    for (int mi = 0; mi < 4; mi++)
#pragma unroll
        for (int ni = 0; ni < 4; ni++)
#pragma unroll
            for (int q = 0; q < 4; q++) acc[mi][ni][q] = 0.f;

    int nIter = p.K >> 4;
    const uint2* Ag = (const uint2*)p.A;
    const uint32_t* AgW = (const uint32_t*)p.A;
    long long aLoW = p.aLo / 2;
    const uint2* Bg = (const uint2*)p.B;

    auto issue = [&](int stage, int chunk) {
        uint32_t base = smemBase + (uint32_t)stage * CA_STAGE_U2 * 8;
        long long ka = (long long)chunk * 8;
        long long kb = (long long)chunk * strideB;
#pragma unroll
        for (int i = 0; i < 4; i++) {
            if (APL) {
                int s4 = szA[i] ? 4 : 0;
                cp_async4(base + sAoff[i],     AgW + gA[i] + ka,        s4);
                cp_async4(base + sAoff[i] + 4, AgW + aLoW + gA[i] + ka, s4);
            } else {
                cp_async8(base + sAoff[i], Ag + gA[i] + ka, szA[i]);
            }
        }
#pragma unroll
        for (int i = 0; i < 4; i++)
            cp_async8(base + sBoff[i], Bg + gB[i] + kb, szB[i]);
    };

#pragma unroll
    for (int s = 0; s < 3; s++) {
        if (s < nIter) issue(s, s);
        asm volatile("cp.async.commit_group;" ::: "memory");
    }

    for (int it = 0; it < nIter; it++) {
        asm volatile("cp.async.wait_group 2;" ::: "memory");
        __syncthreads();
        if (it + 3 < nIter) issue((it + 3) & 3, it + 3);
        asm volatile("cp.async.commit_group;" ::: "memory");

        const uint2* sA = dyn + (it & 3) * CA_STAGE_U2;
        const uint2* sB = sA + 1056;
        uint2 vB0[4], vB1[4];
#pragma unroll
        for (int ni = 0; ni < 4; ni++) {
            int nb2 = wn + ni * 8 + gid;
            vB0[ni] = sB[tg * 132 + nb2];
            vB1[ni] = sB[(tg + 4) * 132 + nb2];
        }
#pragma unroll
        for (int mi = 0; mi < 4; mi++) {
            int mb = wm + mi * 16 + gid;
            uint2 a0 = sA[tg * 132 + mb];
            uint2 a1 = sA[tg * 132 + mb + 8];
            uint2 a2 = sA[(tg + 4) * 132 + mb];
            uint2 a3 = sA[(tg + 4) * 132 + mb + 8];
            uint32_t ah[4] = {a0.x, a1.x, a2.x, a3.x};
            uint32_t al[4] = {a0.y, a1.y, a2.y, a3.y};
#pragma unroll
            for (int ni = 0; ni < 4; ni++) {
                uint32_t bh[2] = {vB0[ni].x, vB1[ni].x};
                mma_f16(acc[mi][ni], ah, bh);
            }
#pragma unroll
            for (int ni = 0; ni < 4; ni++) {
                uint32_t bh[2] = {vB0[ni].x, vB1[ni].x};
                mma_f16(acc[mi][ni], al, bh);
            }
#pragma unroll
            for (int ni = 0; ni < 4; ni++) {
                uint32_t bl[2] = {vB0[ni].y, vB1[ni].y};
                mma_f16(acc[mi][ni], ah, bl);
            }
        }
    }

#pragma unroll
    for (int mi = 0; mi < 4; mi++) {
#pragma unroll
        for (int half = 0; half < 2; half++) {
            int m = m0 + wm + mi * 16 + gid + half * 8;
            if (m >= M) continue;
            long long crow; float w = p.alpha;
            if (p.cRows) {
                crow = (long long)p.cRows[(long long)z * p.cap + m] * p.ldc;
                w *= p.wRow[(long long)z * p.cap + m];
            } else {
                crow = zC + (long long)m * p.ldc;
            }
#pragma unroll
            for (int ni = 0; ni < 4; ni++) {
                int n = n0 + wn + ni * 8 + tg * 2;
                if (n >= p.N) continue;
                float v0 = acc[mi][ni][half * 2 + 0] * w;
                float v1 = acc[mi][ni][half * 2 + 1] * w;
                if (p.cRows) {
                    atomicAdd(&((float*)p.C)[crow + n],     v0);
                    atomicAdd(&((float*)p.C)[crow + n + 1], v1);
                } else if (p.siluPair) {
                    // (v0,v1) = (h1_j, h2_j), j = n/2 : fused silu, plane store
                    float zv = v0 * v1;
                    zv = zv / (1.f + expf(-zv));
                    float sv = zv * SC_;
                    __half hh = __float2half_rn(sv);
                    __half hl = __float2half_rn(sv - __half2float(hh));
                    long long ci = crow + (n >> 1);
                    ((__half*)p.C)[ci]          = hh;
                    ((__half*)p.C)[p.cLoP + ci] = hl;
                } else if (p.outSplit) {
                    ((uint2*)p.C)[crow + (n >> 1)] = split2(v0 * SC_, v1 * SC_);
                } else {
                    float* Cf = (float*)p.C;
                    if (p.res) { v0 += p.res[crow + n]; v1 += p.res[crow + n + 1]; }
                    Cf[crow + n]     = v0;
                    Cf[crow + n + 1] = v1;
                }
            }
        }
    }
}

// ============ raw mma.sync GEMM (fp16-split in loop) — AV only =================
template<int MODE>
__global__ __launch_bounds__(256, 2) void gemm_k(GemmP p) {
    __shared__ uint2 sA[2][8][132];
    __shared__ uint2 sB[2][8][132];

    int z = blockIdx.z, z1 = z / p.zdiv, z2 = z - z1 * p.zdiv;
    const float* A  = (const float*)p.A + z1 * p.aO1 + z2 * p.aO2;
    const float* Bp = (const float*)p.B + z1 * p.bO1 + z2 * p.bO2;
    long long zC = z1 * p.cO1 + z2 * p.cO2;
    int M = p.Mvec ? p.Mvec[z] : p.M;
    int m0 = blockIdx.y * 128, n0 = blockIdx.x * 128;
    if (m0 >= M) return;
    int tid = threadIdx.x, lane = tid & 31, warp = tid >> 5;
    int wm = (warp & 1) << 6, wn = (warp >> 1) << 5;
    int gid = lane >> 2, tg = lane & 3;

    bool aValid; const float* aPtr; int aP, aM;
    if (MODE != 2) {
        int r = m0 + (tid >> 1);
        aValid = (r < M);
        long long ar = 0;
        if (aValid) ar = p.aRows ? (long long)p.aRows[(long long)z * p.cap + r]
                                 : (long long)r;
        aPtr = A + ar * (long long)p.lda + (tid & 1) * 8;
        aP = (tid & 1) * 4;  aM = tid >> 1;
    } else {
        int m = m0 + (tid & 31) * 4;
        aValid = (m < M);
        aPtr = A + (long long)((tid >> 5) * 2) * p.lda + (aValid ? m : 0);
        aP = tid >> 5;       aM = (tid & 31) * 4;
    }
    bool bValid; const float* bPtr; int bP, bM;
    {
        int n = n0 + (tid & 31) * 4;
        bValid = (n < p.N);
        bPtr = Bp + (long long)((tid >> 5) * 2) * p.ldb + (bValid ? n : 0);
        bP = tid >> 5;       bM = (tid & 31) * 4;
    }

    float acc[4][4][4];
#pragma unroll
    for (int mi = 0; mi < 4; mi++)
#pragma unroll
        for (int ni = 0; ni < 4; ni++)
#pragma unroll
            for (int q = 0; q < 4; q++) acc[mi][ni][q] = 0.f;

    const float4 z4 = make_float4(0.f, 0.f, 0.f, 0.f);
    int kStart = (MODE == 2 && p.causalAV) ? m0 : 0;
    int nIter = (p.K - kStart) >> 4;

    auto loadG = [&](int chunk, float4* fa, float4* fb) {
        int k = kStart + chunk * 16;
        if (MODE != 2) {
            fa[0] = aValid ? *(const float4*)(aPtr + k)     : z4;
            fa[1] = aValid ? *(const float4*)(aPtr + k + 4) : z4;
        } else {
            long long o = (long long)k * p.lda;
            fa[0] = aValid ? *(const float4*)(aPtr + o)          : z4;
            fa[1] = aValid ? *(const float4*)(aPtr + o + p.lda)  : z4;
        }
        long long ob = (long long)k * p.ldb;
        fb[0] = bValid ? *(const float4*)(bPtr + ob)         : z4;
        fb[1] = bValid ? *(const float4*)(bPtr + ob + p.ldb) : z4;
    };
    auto storeS = [&](int buf, const float4* fa, const float4* fb) {
        if (MODE != 2) {
            const float* a8 = (const float*)fa;
#pragma unroll
            for (int j = 0; j < 4; j++)
                sA[buf][aP + j][aM] = split2(a8[2*j] * SC_, a8[2*j+1] * SC_);
        } else {
            const float* r0 = (const float*)&fa[0];
            const float* r1 = (const float*)&fa[1];
#pragma unroll
            for (int j = 0; j < 4; j++)
                sA[buf][aP][aM + j] = split2(r0[j] * SC_, r1[j] * SC_);
        }
        const float* b0 = (const float*)&fb[0];
        const float* b1 = (const float*)&fb[1];
#pragma unroll
        for (int j = 0; j < 4; j++)
            sB[buf][bP][bM + j] = split2(b0[j] * SC_, b1[j] * SC_);
    };

    float4 va[2], vb[2];
    loadG(0, va, vb);
    storeS(0, va, vb);
    __syncthreads();

    for (int it = 0; it < nIter; it++) {
        int cur = it & 1;
        float4 na[2] = {z4, z4}, nb[2] = {z4, z4};
        if (it + 1 < nIter) loadG(it + 1, na, nb);

        uint2 vB0[4], vB1[4];
#pragma unroll
        for (int ni = 0; ni < 4; ni++) {
            int nb2 = wn + ni * 8 + gid;
            vB0[ni] = sB[cur][tg    ][nb2];
            vB1[ni] = sB[cur][tg + 4][nb2];
        }
#pragma unroll
        for (int mi = 0; mi < 4; mi++) {
            int mbb = wm + mi * 16 + gid;
            uint2 a0 = sA[cur][tg    ][mbb];
            uint2 a1 = sA[cur][tg    ][mbb + 8];
            uint2 a2 = sA[cur][tg + 4][mbb];
            uint2 a3 = sA[cur][tg + 4][mbb + 8];
            uint32_t ah[4] = {a0.x, a1.x, a2.x, a3.x};
            uint32_t al[4] = {a0.y, a1.y, a2.y, a3.y};
#pragma unroll
            for (int ni = 0; ni < 4; ni++) {
                uint32_t bh[2] = {vB0[ni].x, vB1[ni].x};
                mma_f16(acc[mi][ni], ah, bh);
            }
#pragma unroll
            for (int ni = 0; ni < 4; ni++) {
                uint32_t bh[2] = {vB0[ni].x, vB1[ni].x};
                mma_f16(acc[mi][ni], al, bh);
            }
#pragma unroll
            for (int ni = 0; ni < 4; ni++) {
                uint32_t bl[2] = {vB0[ni].y, vB1[ni].y};
                mma_f16(acc[mi][ni], ah, bl);
            }
        }

        if (it + 1 < nIter) storeS(cur ^ 1, na, nb);
        __syncthreads();
    }

#pragma unroll
    for (int mi = 0; mi < 4; mi++) {
#pragma unroll
        for (int half = 0; half < 2; half++) {
            int m = m0 + wm + mi * 16 + gid + half * 8;
            if (m >= M) continue;
            long long crow; float w = p.alpha;
            if (p.cRows) {
                crow = (long long)p.cRows[(long long)z * p.cap + m] * p.ldc;
                w *= p.wRow[(long long)z * p.cap + m];
            } else {
                crow = zC + (long long)m * p.ldc;
            }
#pragma unroll
            for (int ni = 0; ni < 4; ni++) {
                int n = n0 + wn + ni * 8 + tg * 2;
                if (n >= p.N) continue;
                float v0 = acc[mi][ni][half * 2 + 0] * w;
                float v1 = acc[mi][ni][half * 2 + 1] * w;
                if (p.cRows) {
                    atomicAdd(&((float*)p.C)[crow + n],     v0);
                    atomicAdd(&((float*)p.C)[crow + n + 1], v1);
                } else if (p.outSplit) {
                    ((uint2*)p.C)[crow + (n >> 1)] = split2(v0 * SC_, v1 * SC_);
                } else {
                    float* Cf = (float*)p.C;
                    if (p.res) { v0 += p.res[crow + n]; v1 += p.res[crow + n + 1]; }
                    Cf[crow + n]     = v0;
                    Cf[crow + n + 1] = v1;
                }
            }
        }
    }
}

// ---------------- producers / small kernels ------------------------------------
__global__ void split_arr_k(const float4* __restrict__ in, uint2* __restrict__ out,
                            long long n4) {
    long long i = (long long)blockIdx.x * 256 + threadIdx.x;
    if (i >= n4) return;
    float4 v = in[i];
    out[2 * i]     = split2(v.x * SC_, v.y * SC_);
    out[2 * i + 1] = split2(v.z * SC_, v.w * SC_);
}

// NN pair pack w/ column stride: out[p*ldout + colOff + n*colStride]
__global__ void split_pack_nn_k(const float* __restrict__ in, uint2* __restrict__ out,
                                long long total, int N, int ldout, int colOff,
                                int colStride) {
    long long i = (long long)blockIdx.x * 256 + threadIdx.x;
    if (i >= total) return;
    long long pr = i / N;
    int n = (int)(i - pr * N);
    out[pr * ldout + colOff + (long long)n * colStride] =
        split2(in[(2 * pr) * N + n] * SC_, in[(2 * pr + 1) * N + n] * SC_);
}

__global__ void reduce_split_k(const float* __restrict__ p0, const float* __restrict__ p1,
                               uint2* __restrict__ out, long long npair) {
    long long i = (long long)blockIdx.x * 256 + threadIdx.x;
    if (i >= npair) return;
    float v0 = p0[2*i]   + p1[2*i];
    float v1 = p0[2*i+1] + p1[2*i+1];
    out[i] = split2(v0 * SC_, v1 * SC_);
}

__global__ void rmsnorm_k(const float* __restrict__ x, const float* __restrict__ w,
                          float* __restrict__ oraw, uint2* __restrict__ osp) {
    int r = blockIdx.x;
    const float* xr = x + (long long)r * DIM_;
    float s = 0.f;
    for (int d = threadIdx.x; d < DIM_; d += 256) { float v = xr[d]; s += v * v; }
    __shared__ float red[256];
    red[threadIdx.x] = s; __syncthreads();
    for (int off = 128; off; off >>= 1) {
        if (threadIdx.x < off) red[threadIdx.x] += red[threadIdx.x + off];
        __syncthreads();
    }
    float inv = rsqrtf(red[0] / (float)DIM_ + 1e-6f);
    for (int pd = threadIdx.x; pd < DIM_/2; pd += 256) {
        int d = pd * 2;
        float v0 = w[d] * xr[d] * inv;
        float v1 = w[d+1] * xr[d+1] * inv;
        if (oraw) { oraw[(long long)r * DIM_ + d] = v0; oraw[(long long)r * DIM_ + d+1] = v1; }
        osp[(long long)r * (DIM_/2) + pd] = split2(v0 * SC_, v1 * SC_);
    }
}

__device__ __forceinline__ void rope_cs(int t, int j, float& c, float& s) {
    float freq = 1.0f / powf(10000.0f, (float)(2 * j) / (float)DRH_);
    float ang = (float)t * freq;
    sincosf(ang, &s, &c);
}
__device__ __forceinline__ void unpack2(uint2 u, float& a, float& b) {
    __half2 h = *(__half2*)&u.x, l = *(__half2*)&u.y;
    a = __low2float(h) + __low2float(l);
    b = __high2float(h) + __high2float(l);
}

__global__ void rope_q_k(uint2* __restrict__ Q) {
    int idx = blockIdx.x;
    int bt = idx / NH_;
    int t = bt % T_;
    int pp = threadIdx.x;
    uint2* base = Q + (long long)idx * (QKD_/2) + DH_/2;
    float re0, re1, im0, im1;
    unpack2(base[pp], re0, re1);
    unpack2(base[16 + pp], im0, im1);
    float c0, s0, c1, s1;
    rope_cs(t, 2*pp, c0, s0); rope_cs(t, 2*pp + 1, c1, s1);
    base[pp]      = split2(re0 * c0 - im0 * s0, re1 * c1 - im1 * s1);
    base[16 + pp] = split2(re0 * s0 + im0 * c0, re1 * s1 + im1 * c1);
}

__global__ void rope_kr_k(const uint2* __restrict__ cdq, uint2* __restrict__ Kb) {
    int bt = blockIdx.x;
    int t = bt % T_;
    int pp = threadIdx.x;
    const uint2* src = cdq + (long long)bt * (NCDQ_/2) + 512;
    float re0, re1, im0, im1;
    unpack2(src[pp], re0, re1);
    unpack2(src[16 + pp], im0, im1);
    float c0, s0, c1, s1;
    rope_cs(t, 2*pp, c0, s0); rope_cs(t, 2*pp + 1, c1, s1);
    float inh = 1.0f / (float)NH_;
    uint2 o1 = split2((re0 * c0 - im0 * s0) * inh, (re1 * c1 - im1 * s1) * inh);
    uint2 o2 = split2((re0 * s0 + im0 * c0) * inh, (re1 * s1 + im1 * c1) * inh);
    for (int h = 0; h < NH_; h++) {
        uint2* base = Kb + ((long long)bt * NH_ + h) * (QKD_/2) + DH_/2;
        base[pp] = o1; base[16 + pp] = o2;
    }
}

__global__ void softmax_k(float* __restrict__ S) {
    long long r = blockIdx.x;
    int t = (int)(r & (T_ - 1));
    float* row = S + r * (long long)T_;
    int n = t + 1;
    __shared__ float red[256];
    int tid = threadIdx.x;
    float mx = -INFINITY;
    for (int l = tid; l < n; l += 256) mx = fmaxf(mx, row[l]);
    red[tid] = mx; __syncthreads();
    for (int off = 128; off; off >>= 1) {
        if (tid < off) red[tid] = fmaxf(red[tid], red[tid + off]);
        __syncthreads();
    }
    mx = red[0]; __syncthreads();
    float sum = 0.f;
    for (int l = tid; l < n; l += 256) { float e = expf(row[l] - mx); row[l] = e; sum += e; }
    red[tid] = sum; __syncthreads();
    for (int off = 128; off; off >>= 1) {
        if (tid < off) red[tid] += red[tid + off];
        __syncthreads();
    }
    float inv = 1.f / red[0];
    for (int l = tid; l < T_; l += 256) row[l] = (l < n) ? row[l] * inv : 0.f;
}

__global__ void pack_wo_k(const float* __restrict__ wo, uint2* __restrict__ out) {
    long long i = (long long)blockIdx.x * 256 + threadIdx.x;
    if (i >= (long long)DIM_ * 1024) return;
    int d = (int)(i >> 10);
    int pr = (int)(i & 1023);
    int e = pr * 2;
    int h = e >> 7, k = e & 127;
    float s0 = wo[(long long)d * 2048 + k * NH_ + h];
    float s1 = wo[(long long)d * 2048 + (k + 1) * NH_ + h];
    out[i] = split2(s0 * SC_, s1 * SC_);
}

__global__ void gate_k(const float* __restrict__ xn, const float* __restrict__ gw,
                       const float* __restrict__ gb, float* affOut,
                       int* __restrict__ cnt, int* __restrict__ tok,
                       float* __restrict__ wt) {
    int bt = blockIdx.x;
    __shared__ float xrow[DIM_];
    __shared__ float aff[NE_];
    int tid = threadIdx.x;
    for (int d = tid; d < DIM_; d += 256) xrow[d] = xn[(long long)bt * DIM_ + d];
    __syncthreads();
    int w = tid >> 5, lane = tid & 31;
    for (int e = w; e < NE_; e += 8) {
        float s = 0.f;
        const float* gr = gw + (long long)e * DIM_;
        for (int d = lane; d < DIM_; d += 32) s += xrow[d] * gr[d];
        for (int o = 16; o; o >>= 1) s += __shfl_xor_sync(0xffffffffu, s, o);
        if (lane == 0) aff[e] = 1.f / (1.f + expf(-s)) + gb[e];
    }
    __syncthreads();
    if (tid == 0) {
        if (affOut) for (int e = 0; e < NE_; e++) affOut[(long long)bt * NE_ + e] = aff[e];
        bool used[NE_] = {};
        float wv[TOPK_]; int wi[TOPK_]; float sum = 0.f;
        for (int k = 0; k < TOPK_; k++) {
            float best = -1e30f; int bi = 0;
            for (int e = 0; e < NE_; e++)
                if (!used[e] && aff[e] > best) { best = aff[e]; bi = e; }
            used[bi] = true; wv[k] = best; wi[k] = bi; sum += best;
        }
        for (int k = 0; k < TOPK_; k++) {
            int e = wi[k];
            int pos = atomicAdd(&cnt[e], 1);
            tok[e * CAP_ + pos] = bt;
            wt [e * CAP_ + pos] = wv[k] / sum;
        }
    }
}

// ---------------- host helpers ------------------------------------------------
static GemmP mkP(const void* A, const void* B, void* C, int M, int N, int K,
                 int lda, int ldb, int ldc, float alpha, const float* res,
                 int zdiv, long long a1, long long a2, long long b1, long long b2,
                 long long c1, long long c2,
                 const int* Mvec, const int* aRows, const int* cRows,
                 const float* wRow, int cap, int causal, int causalAV, int outSplit,
                 long long aLo = 0, int siluPair = 0, long long cLoP = 0) {
    GemmP p;
    p.A = A; p.B = B; p.C = C; p.res = res;
    p.M = M; p.N = N; p.K = K; p.lda = lda; p.ldb = ldb; p.ldc = ldc;
    p.aLo = aLo; p.alpha = alpha;
    p.aO1 = a1; p.aO2 = a2; p.bO1 = b1; p.bO2 = b2; p.cO1 = c1; p.cO2 = c2;
    p.zdiv = zdiv; p.cap = cap;
    p.Mvec = Mvec; p.aRows = aRows; p.cRows = cRows; p.wRow = wRow;
    p.causal = causal; p.causalAV = causalAV; p.outSplit = outSplit;
    p.siluPair = siluPair; p.cLoP = cLoP;
    return p;
}

template<int MODE, int APL>
static void gemmCA(const void* A, const uint2* B, void* C, int M, int N, int K,
                   int ldaP, int ldbP, int ldc, float alpha, const float* res,
                   int nz, int zdiv,
                   long long a1, long long a2, long long b1, long long b2,
                   long long c1, long long c2,
                   int causal = 0, int outSplit = 0,
                   const int* Mvec = nullptr, const int* aRows = nullptr,
                   const int* cRows = nullptr, const float* wRow = nullptr,
                   int cap = 0, int mBlocks = 0,
                   long long aLo = 0, int siluPair = 0, long long cLoP = 0) {
    GemmP p = mkP(A, B, C, M, N, K, ldaP, ldbP, ldc, alpha, res, zdiv,
                  a1, a2, b1, b2, c1, c2,
                  Mvec, aRows, cRows, wRow, cap, causal, 0, outSplit,
                  aLo, siluPair, cLoP);
    cudaFuncSetAttribute(gemm_ca<MODE, APL>, cudaFuncAttributeMaxDynamicSharedMemorySize,
                         CA_SMEM_BYTES);
    int gy = mBlocks ? mBlocks : (M + 127) / 128;
    dim3 g((N + 127) / 128, gy, nz);
    gemm_ca<MODE, APL><<<g, 256, CA_SMEM_BYTES>>>(p);
}

template<int MODE>
static void gemmRaw(const float* A, const float* B, void* C, int M, int N, int K,
                    int lda, int ldb, int ldc, float alpha, const float* res,
                    int nz, int zdiv,
                    long long a1, long long a2, long long b1, long long b2,
                    long long c1, long long c2,
                    const int* Mvec = nullptr, const int* aRows = nullptr,
                    const int* cRows = nullptr, const float* wRow = nullptr,
                    int cap = 0, int causalAV = 0, int outSplit = 0) {
    GemmP p = mkP(A, B, C, M, N, K, lda, ldb, ldc, alpha, res, zdiv,
                  a1, a2, b1, b2, c1, c2,
                  Mvec, aRows, cRows, wRow, cap, 0, causalAV, outSplit);
    dim3 g((N + 127) / 128, (M + 127) / 128, nz);
    gemm_k<MODE><<<g, 256>>>(p);
}

static void splitArr(const float* in, uint2* out, long long n) {
    long long n4 = n >> 2;
    split_arr_k<<<(unsigned)((n4 + 255) / 256), 256>>>((const float4*)in, out, n4);
}

extern "C" void kernel_launch(void* const* d_in, const int* in_sizes, int n_in,
                              void* d_out, int out_size) {
    const float* x      = (const float*)d_in[0];
    const float* attn_w = (const float*)d_in[3];
    const float* ffn_w  = (const float*)d_in[4];
    const float* gate_w = (const float*)d_in[5];
    const float* gate_b = (const float*)d_in[6];
    const float* w1s    = (const float*)d_in[7];
    const float* w2s    = (const float*)d_in[8];
    const float* w3s    = (const float*)d_in[9];
    const float* w1r    = (const float*)d_in[10];
    const float* w2r    = (const float*)d_in[11];
    const float* w3r    = (const float*)d_in[12];
    const float* wdkv   = (const float*)d_in[13];
    const float* wuk    = (const float*)d_in[14];
    const float* wuv    = (const float*)d_in[15];
    const float* wdq    = (const float*)d_in[16];
    const float* wuq    = (const float*)d_in[17];
    const float* wqr    = (const float*)d_in[18];
    const float* wkr    = (const float*)d_in[19];
    const float* wo     = (const float*)d_in[20];
    float* out = (float*)d_out;

    float *S, *V, *x1, *xn, *pk, *wt;
    int *cnt, *tok;
    uint2 *h2, *cdq2, *Q2, *K2, *O2, *Wo2, *xn2;
    __half *a1P, *h1P;
    uint2 *wA2, *wuk2, *wuv2, *wuq2, *wqr2, *w13s2, *w2s2, *w13r2, *w2r2;
    cudaGetSymbolAddress((void**)&S,   g_S);
    cudaGetSymbolAddress((void**)&V,   g_V);
    cudaGetSymbolAddress((void**)&x1,  g_x1);
    cudaGetSymbolAddress((void**)&xn,  g_xn);
    cudaGetSymbolAddress((void**)&pk,  g_pk);
    cudaGetSymbolAddress((void**)&cnt, g_cnt);
    cudaGetSymbolAddress((void**)&tok, g_tok);
    cudaGetSymbolAddress((void**)&wt,  g_wt);
    cudaGetSymbolAddress((void**)&h2,  g_h2);
    cudaGetSymbolAddress((void**)&cdq2, g_cdq2);
    cudaGetSymbolAddress((void**)&Q2,  g_Q2);
    cudaGetSymbolAddress((void**)&K2,  g_K2);
    cudaGetSymbolAddress((void**)&O2,  g_O2);
    cudaGetSymbolAddress((void**)&Wo2, g_Wo2);
    cudaGetSymbolAddress((void**)&xn2, g_xn2);
    cudaGetSymbolAddress((void**)&a1P, g_a1P);
    cudaGetSymbolAddress((void**)&h1P, g_h1P);
    cudaGetSymbolAddress((void**)&wA2,  g_wA2);
    cudaGetSymbolAddress((void**)&wuk2, g_wuk2);
    cudaGetSymbolAddress((void**)&wuv2, g_wuv2);
    cudaGetSymbolAddress((void**)&wuq2, g_wuq2);
    cudaGetSymbolAddress((void**)&wqr2, g_wqr2);
    cudaGetSymbolAddress((void**)&w13s2, g_w13s2);
    cudaGetSymbolAddress((void**)&w2s2,  g_w2s2);
    cudaGetSymbolAddress((void**)&w13r2, g_w13r2);
    cudaGetSymbolAddress((void**)&w2r2,  g_w2r2);

    const long long E_a1 = (long long)BT_ * MOESH_;
    const long long E_h1 = (long long)NE_ * CAP_ * MOE_;

    // ---- weight pre-split / packing ----
    splitArr(wdkv, wA2,                           (long long)DC_*DIM_);
    splitArr(wdq,  wA2 + (long long)DC_*DIM_/2,   (long long)DC_*DIM_);
    splitArr(wkr,  wA2 + (long long)DC_*DIM_,     (long long)DRH_*DIM_);
    splitArr(wuk,  wuk2, (long long)DH_*NH_*DC_);
    splitArr(wuv,  wuv2, (long long)DH_*NH_*DC_);
    splitArr(wuq,  wuq2, (long long)DH_*NH_*DC_);
    splitArr(wqr,  wqr2, (long long)DRH_*NH_*DC_);
    {   // shared FFN: w1/w3 INTERLEAVED columns for fused-silu epilogue
        long long tot = (long long)(DIM_/2) * MOESH_;
        unsigned nb = (unsigned)((tot + 255) / 256);
        split_pack_nn_k<<<nb, 256>>>(w1s, w13s2, tot, MOESH_, 2*MOESH_, 0, 2);
        split_pack_nn_k<<<nb, 256>>>(w3s, w13s2, tot, MOESH_, 2*MOESH_, 1, 2);
        long long tot2 = (long long)(MOESH_/2) * DIM_;
        split_pack_nn_k<<<(unsigned)((tot2 + 255)/256), 256>>>(w2s, w2s2, tot2, DIM_, DIM_, 0, 1);
    }
    {   // routed: interleaved w1r/w3r
        long long totr = (long long)NE_ * (DIM_/2) * MOE_;
        unsigned nbr = (unsigned)((totr + 255) / 256);
        split_pack_nn_k<<<nbr, 256>>>(w1r, w13r2, totr, MOE_, 2*MOE_, 0, 2);
        split_pack_nn_k<<<nbr, 256>>>(w3r, w13r2, totr, MOE_, 2*MOE_, 1, 2);
        long long totr2 = (long long)NE_ * (MOE_/2) * DIM_;
        split_pack_nn_k<<<(unsigned)((totr2 + 255)/256), 256>>>(w2r, w2r2, totr2, DIM_, DIM_, 0, 1);
    }
    pack_wo_k<<<(unsigned)(((long long)DIM_*1024 + 255)/256), 256>>>(wo, Wo2);

    // ---- attention ----
    rmsnorm_k<<<BT_, 256>>>(x, attn_w, nullptr, h2);
    gemmCA<1,0>(h2, wA2, pk, BT_, NCDQ_, DIM_/2, DIM_/2, DIM_/2, NCDQ_, ASC_, nullptr,
                2, 1, /*aO1=*/DIM_/4, 0, /*bO1=*/DIM_/4, 0,
                /*cO1=*/(long long)BT_*NCDQ_, 0, 0, 0);
    {
        long long np = (long long)BT_*NCDQ_/2;
        reduce_split_k<<<(unsigned)((np + 255)/256), 256>>>(pk, pk + (long long)BT_*NCDQ_, cdq2, np);
    }
    gemmCA<1,0>(cdq2, wuk2, K2, BT_, DH_, DC_, NCDQ_/2, NH_*DC_/2, NH_*QKD_/2, ASC_, nullptr,
                NH_, NH_, 0,0, 0, DC_/2, 0, QKD_/2, 0, 1);
    gemmCA<1,0>(cdq2, wuv2, (void*)V, BT_, DH_, DC_, NCDQ_/2, NH_*DC_/2, NH_*DH_, ASC_, nullptr,
                NH_, NH_, 0,0, 0, DC_/2, 0, DH_, 0, 0);
    gemmCA<1,0>(cdq2 + DC_/2, wuq2, Q2, BT_, DH_, DC_, NCDQ_/2, NH_*DC_/2, NH_*QKD_/2,
                ASC_, nullptr, NH_, NH_, 0,0, 0, DC_/2, 0, QKD_/2, 0, 1);
    gemmCA<1,0>(cdq2 + DC_/2, wqr2, Q2 + DH_/2, BT_, DRH_, DC_, NCDQ_/2, NH_*DC_/2, NH_*QKD_/2,
                ASC_, nullptr, NH_, NH_, 0,0, 0, DC_/2, 0, QKD_/2, 0, 1);
    rope_q_k<<<BT_ * NH_, 16>>>(Q2);
    rope_kr_k<<<BT_, 16>>>(cdq2, K2);
    float scale = ASC_ / sqrtf((float)QKD_);
    gemmCA<1,0>(Q2, K2, S, T_, T_, QKD_, NH_*QKD_/2, NH_*QKD_/2, T_, scale, nullptr,
                B_*NH_, NH_,
                (long long)T_*NH_*QKD_/2, QKD_/2,
                (long long)T_*NH_*QKD_/2, QKD_/2,
                (long long)NH_*T_*T_, (long long)T_*T_,
                /*causal=*/1, 0);
    softmax_k<<<B_ * NH_ * T_, 256>>>(S);
    gemmRaw<2>(S, V, O2, T_, DH_, T_, T_, NH_*DH_, NH_*DH_/2, ASC_, nullptr,
               B_*NH_, NH_,
               (long long)NH_*T_*T_, (long long)T_*T_,
               (long long)T_*NH_*DH_, DH_,
               (long long)T_*NH_*DH_/2, DH_/2,
               nullptr, nullptr, nullptr, nullptr, 0, /*causalAV=*/1, /*outSplit=*/1);
    gemmCA<1,0>(O2, Wo2, x1, BT_, DIM_, NH_*DH_, NH_*DH_/2, NH_*DH_/2, DIM_, ASC_, x,
                1, 1, 0,0,0,0,0,0, 0, 0);

    // ---- MoE ----
    rmsnorm_k<<<BT_, 256>>>(x1, ffn_w, xn, xn2);
    cudaMemsetAsync(cnt, 0, NE_ * sizeof(int));
    float* affOut = (out_size >= BT_*DIM_ + BT_*NE_) ? out + (long long)BT_*DIM_ : nullptr;
    gate_k<<<BT_, 256>>>(xn, gate_w, gate_b, affOut, cnt, tok, wt);
    // shared FFN up + fused silu -> a1P planes
    gemmCA<0,0>(xn2, w13s2, a1P, BT_, 2*MOESH_, DIM_, DIM_/2, 2*MOESH_, MOESH_, ASC_, nullptr,
                1, 1, 0,0,0,0,0,0, 0, 0,
                nullptr, nullptr, nullptr, nullptr, 0, 0,
                0, /*siluPair=*/1, /*cLoP=*/E_a1);
    // shared FFN down (A = planes)
    gemmCA<0,1>(a1P, w2s2, out, BT_, DIM_, MOESH_, MOESH_, DIM_, DIM_, ASC_, x1,
                1, 1, 0,0,0,0,0,0, 0, 0,
                nullptr, nullptr, nullptr, nullptr, 0, 0, /*aLo=*/E_a1);
    // routed up + fused silu -> h1P planes
    gemmCA<0,0>(xn2, w13r2, h1P, CAP_, 2*MOE_, DIM_, DIM_/2, 2*MOE_, MOE_, ASC_, nullptr,
                NE_, NE_, 0,0, 0, (long long)(DIM_/2)*2*MOE_, 0, (long long)CAP_*MOE_,
                0, 0, cnt, tok, nullptr, nullptr, CAP_, CAP_/128,
                0, /*siluPair=*/1, /*cLoP=*/E_h1);
    // routed down (A = planes), weighted atomic scatter
    gemmCA<0,1>(h1P, w2r2, out, CAP_, DIM_, MOE_, MOE_, DIM_, DIM_, ASC_, nullptr,
                NE_, NE_, 0, (long long)CAP_*MOE_, 0, (long long)(MOE_/2)*DIM_, 0, 0,
                0, 0, cnt, nullptr, tok, wt, CAP_, CAP_/128, /*aLo=*/E_h1);
}

// round 16
// speedup vs baseline: 1.0199x; 1.0199x over previous
#include <cuda_runtime.h>
#include <cuda_fp16.h>
#include <math.h>
#include <stdint.h>

#define B_    2
#define T_    1024
#define BT_   2048
#define DIM_  2048
#define NH_   16
#define DH_   128
#define DRH_  64
#define DC_   512
#define NE_   16
#define TOPK_ 4
#define MOE_  1024
#define MOESH_ 2048
#define CAP_  2048
#define QKD_  192
#define NCDQ_ 1088
#define SC_   256.0f
#define ASC_  (1.0f/65536.0f)

// ---------------- scratch ----------------
__device__ float g_S  [(size_t)B_*NH_*T_*T_];
__device__ float g_V  [BT_*NH_*DH_];
__device__ float g_x1 [BT_*DIM_];
__device__ float g_xn [BT_*DIM_];
__device__ float g_pk [2][(size_t)BT_*NCDQ_];
__device__ int   g_cnt[NE_];
__device__ int   g_tok[NE_*CAP_];
__device__ float g_wt [NE_*CAP_];
// fp16 pair-split buffers (uint2 = (hi2,lo2) of k,k+1), values x*256
__device__ __align__(16) uint2 g_h2  [BT_*DIM_/2];
__device__ __align__(16) uint2 g_cdq2[(size_t)BT_*NCDQ_/2];
__device__ __align__(16) uint2 g_Q2  [BT_*NH_*QKD_/2];
__device__ __align__(16) uint2 g_K2  [BT_*NH_*QKD_/2];
__device__ __align__(16) uint2 g_O2  [BT_*NH_*DH_/2];
__device__ __align__(16) uint2 g_Wo2 [(size_t)DIM_*NH_*DH_/2];
__device__ __align__(16) uint2 g_xn2 [BT_*DIM_/2];
__device__ __align__(16) uint2 g_a1s [BT_*MOESH_/2];
__device__ __align__(16) uint2 g_h1S [(size_t)NE_*CAP_*MOE_/2];
// split weights
__device__ __align__(16) uint2 g_wA2  [(size_t)NCDQ_*DIM_/2];
__device__ __align__(16) uint2 g_wuk2 [DH_*NH_*DC_/2];
__device__ __align__(16) uint2 g_wuv2 [DH_*NH_*DC_/2];
__device__ __align__(16) uint2 g_wuq2 [DH_*NH_*DC_/2];
__device__ __align__(16) uint2 g_wqr2 [DRH_*NH_*DC_/2];
__device__ __align__(16) uint2 g_w13s2[(size_t)(DIM_/2)*2*MOESH_];
__device__ __align__(16) uint2 g_w2s2 [(size_t)(MOESH_/2)*DIM_];
__device__ __align__(16) uint2 g_w13r2[(size_t)NE_*(DIM_/2)*2*MOE_];
__device__ __align__(16) uint2 g_w2r2 [(size_t)NE_*(MOE_/2)*DIM_];

__device__ __forceinline__ uint2 split2(float x, float y) {
    __half hx = __float2half_rn(x), hy = __float2half_rn(y);
    float lx = x - __half2float(hx), ly = y - __half2float(hy);
    __half2 h = __halves2half2(hx, hy);
    __half2 l = __halves2half2(__float2half_rn(lx), __float2half_rn(ly));
    uint2 r; r.x = *(uint32_t*)&h; r.y = *(uint32_t*)&l;
    return r;
}
__device__ __forceinline__ void mma_f16(float* c, const uint32_t* a, const uint32_t* b) {
    asm volatile("mma.sync.aligned.m16n8k16.row.col.f32.f16.f16.f32 "
        "{%0,%1,%2,%3}, {%4,%5,%6,%7}, {%8,%9}, {%0,%1,%2,%3};\n"
        : "+f"(c[0]), "+f"(c[1]), "+f"(c[2]), "+f"(c[3])
        : "r"(a[0]), "r"(a[1]), "r"(a[2]), "r"(a[3]), "r"(b[0]), "r"(b[1]));
}

struct GemmP {
    const void* A; const void* B; void* C; const float* res;
    int M, N, K, lda, ldb, ldc;   // pair strides for split ops; floats for raw
    float alpha;
    long long aO1, aO2, bO1, bO2, cO1, cO2;
    int zdiv, cap;
    const int* Mvec; const int* aRows; const int* cRows; const float* wRow;
    int causal, causalAV, outSplit, siluPair;
};

// ============ cp.async GEMM (pair-split operands) ==============================
#define CA_STAGE_U2 2112
#define CA_SMEM_BYTES (4 * CA_STAGE_U2 * 8)

__device__ __forceinline__ void cp_async8(uint32_t saddr, const void* gaddr, int sz) {
    asm volatile("cp.async.ca.shared.global [%0], [%1], 8, %2;"
                 :: "r"(saddr), "l"(gaddr), "r"(sz) : "memory");
}

template<int MODE>
__global__ __launch_bounds__(256, 2) void gemm_ca(GemmP p) {
    extern __shared__ uint2 dyn[];
    uint32_t smemBase = (uint32_t)__cvta_generic_to_shared(dyn);

    int z = blockIdx.z, z1 = z / p.zdiv, z2 = z - z1 * p.zdiv;
    long long zA = z1 * p.aO1 + z2 * p.aO2;
    long long zB = z1 * p.bO1 + z2 * p.bO2;
    long long zC = z1 * p.cO1 + z2 * p.cO2;
    int M = p.Mvec ? p.Mvec[z] : p.M;
    int m0 = blockIdx.y * 128, n0 = blockIdx.x * 128;
    if (m0 >= M) return;
    if (MODE == 1 && p.causal && n0 >= m0 + 128) return;
    int tid = threadIdx.x, lane = tid & 31, warp = tid >> 5;
    int wm = (warp & 1) << 6, wn = (warp >> 1) << 5;
    int gid = lane >> 2, tg = lane & 3;

    long long gA[4]; uint32_t sAoff[4]; int szA[4];
    long long gB[4]; uint32_t sBoff[4]; int szB[4];
    long long strideB = (MODE == 1) ? 8 : (long long)8 * p.ldb;
#pragma unroll
    for (int i = 0; i < 4; i++) {
        int e = tid + 256 * i;
        int am = e >> 3, ak = e & 7;
        int row = m0 + am;
        bool va = row < M;
        long long ar = 0;
        if (va) ar = p.aRows ? (long long)p.aRows[(long long)z * p.cap + row]
                             : (long long)row;
        gA[i] = zA + ar * p.lda + ak;
        sAoff[i] = (uint32_t)(ak * 132 + am) * 8;
        szA[i] = va ? 8 : 0;
        if (MODE == 1) {
            int bn = e >> 3, bk = e & 7;
            bool vb = (n0 + bn) < p.N;
            gB[i] = zB + (long long)(vb ? (n0 + bn) : 0) * p.ldb + bk;
            sBoff[i] = (uint32_t)(1056 + bk * 132 + bn) * 8;
            szB[i] = vb ? 8 : 0;
        } else {
            int bk = e >> 7, bn = e & 127;
            bool vb = (n0 + bn) < p.N;
            gB[i] = zB + (long long)bk * p.ldb + n0 + (vb ? bn : 0);
            sBoff[i] = (uint32_t)(1056 + bk * 132 + bn) * 8;
            szB[i] = vb ? 8 : 0;
        }
    }

    float acc[4][4][4];
#pragma unroll
    for (int mi = 0; mi < 4; mi++)
#pragma unroll
        for (int ni = 0; ni < 4; ni++)
#pragma unroll
            for (int q = 0; q < 4; q++) acc[mi][ni][q] = 0.f;

    int nIter = p.K >> 4;
    const uint2* Ag = (const uint2*)p.A;
    const uint2* Bg = (const uint2*)p.B;

    auto issue = [&](int stage, int chunk) {
        uint32_t base = smemBase + (uint32_t)stage * CA_STAGE_U2 * 8;
        long long ka = (long long)chunk * 8;
        long long kb = (long long)chunk * strideB;
#pragma unroll
        for (int i = 0; i < 4; i++)
            cp_async8(base + sAoff[i], Ag + gA[i] + ka, szA[i]);
#pragma unroll
        for (int i = 0; i < 4; i++)
            cp_async8(base + sBoff[i], Bg + gB[i] + kb, szB[i]);
    };

#pragma unroll
    for (int s = 0; s < 3; s++) {
        if (s < nIter) issue(s, s);
        asm volatile("cp.async.commit_group;" ::: "memory");
    }

    for (int it = 0; it < nIter; it++) {
        asm volatile("cp.async.wait_group 2;" ::: "memory");
        __syncthreads();
        if (it + 3 < nIter) issue((it + 3) & 3, it + 3);
        asm volatile("cp.async.commit_group;" ::: "memory");

        const uint2* sA = dyn + (it & 3) * CA_STAGE_U2;
        const uint2* sB = sA + 1056;
        uint2 vB0[4], vB1[4];
#pragma unroll
        for (int ni = 0; ni < 4; ni++) {
            int nb2 = wn + ni * 8 + gid;
            vB0[ni] = sB[tg * 132 + nb2];
            vB1[ni] = sB[(tg + 4) * 132 + nb2];
        }
#pragma unroll
        for (int mi = 0; mi < 4; mi++) {
            int mb = wm + mi * 16 + gid;
            uint2 a0 = sA[tg * 132 + mb];
            uint2 a1 = sA[tg * 132 + mb + 8];
            uint2 a2 = sA[(tg + 4) * 132 + mb];
            uint2 a3 = sA[(tg + 4) * 132 + mb + 8];
            uint32_t ah[4] = {a0.x, a1.x, a2.x, a3.x};
            uint32_t al[4] = {a0.y, a1.y, a2.y, a3.y};
#pragma unroll
            for (int ni = 0; ni < 4; ni++) {
                uint32_t bh[2] = {vB0[ni].x, vB1[ni].x};
                mma_f16(acc[mi][ni], ah, bh);
            }
#pragma unroll
            for (int ni = 0; ni < 4; ni++) {
                uint32_t bh[2] = {vB0[ni].x, vB1[ni].x};
                mma_f16(acc[mi][ni], al, bh);
            }
#pragma unroll
            for (int ni = 0; ni < 4; ni++) {
                uint32_t bl[2] = {vB0[ni].y, vB1[ni].y};
                mma_f16(acc[mi][ni], ah, bl);
            }
        }
    }

#pragma unroll
    for (int mi = 0; mi < 4; mi++) {
#pragma unroll
        for (int half = 0; half < 2; half++) {
            int m = m0 + wm + mi * 16 + gid + half * 8;
            bool mvalid = (m < M);
            if (!p.siluPair && !mvalid) continue;
            long long crow = 0; float w = p.alpha;
            if (mvalid) {
                if (p.cRows) {
                    crow = (long long)p.cRows[(long long)z * p.cap + m] * p.ldc;
                    w *= p.wRow[(long long)z * p.cap + m];
                } else {
                    crow = zC + (long long)m * p.ldc;
                }
            }
#pragma unroll
            for (int ni = 0; ni < 4; ni++) {
                int n = n0 + wn + ni * 8 + tg * 2;
                float v0 = acc[mi][ni][half * 2 + 0] * w;
                float v1 = acc[mi][ni][half * 2 + 1] * w;
                if (p.siluPair) {
                    // (v0,v1) = (h1_j, h2_j): fused silu; pair via shuffle
                    float zv = v0 * v1;
                    zv = zv / (1.f + expf(-zv));
                    float sv = zv * SC_;
                    float svn = __shfl_down_sync(0xffffffffu, sv, 1);
                    if (mvalid && ((tg & 1) == 0) && n < p.N)
                        ((uint2*)p.C)[crow + (n >> 2)] = split2(sv, svn);
                    continue;
                }
                if (n >= p.N) continue;
                if (p.cRows) {
                    atomicAdd(&((float*)p.C)[crow + n],     v0);
                    atomicAdd(&((float*)p.C)[crow + n + 1], v1);
                } else if (p.outSplit) {
                    ((uint2*)p.C)[crow + (n >> 1)] = split2(v0 * SC_, v1 * SC_);
                } else {
                    float* Cf = (float*)p.C;
                    if (p.res) { v0 += p.res[crow + n]; v1 += p.res[crow + n + 1]; }
                    Cf[crow + n]     = v0;
                    Cf[crow + n + 1] = v1;
                }
            }
        }
    }
}

// ============ raw mma.sync GEMM (fp16-split in loop) — AV only =================
template<int MODE>
__global__ __launch_bounds__(256, 2) void gemm_k(GemmP p) {
    __shared__ uint2 sA[2][8][132];
    __shared__ uint2 sB[2][8][132];

    int z = blockIdx.z, z1 = z / p.zdiv, z2 = z - z1 * p.zdiv;
    const float* A  = (const float*)p.A + z1 * p.aO1 + z2 * p.aO2;
    const float* Bp = (const float*)p.B + z1 * p.bO1 + z2 * p.bO2;
    long long zC = z1 * p.cO1 + z2 * p.cO2;
    int M = p.Mvec ? p.Mvec[z] : p.M;
    int m0 = blockIdx.y * 128, n0 = blockIdx.x * 128;
    if (m0 >= M) return;
    int tid = threadIdx.x, lane = tid & 31, warp = tid >> 5;
    int wm = (warp & 1) << 6, wn = (warp >> 1) << 5;
    int gid = lane >> 2, tg = lane & 3;

    bool aValid; const float* aPtr; int aP, aM;
    if (MODE != 2) {
        int r = m0 + (tid >> 1);
        aValid = (r < M);
        long long ar = 0;
        if (aValid) ar = p.aRows ? (long long)p.aRows[(long long)z * p.cap + r]
                                 : (long long)r;
        aPtr = A + ar * (long long)p.lda + (tid & 1) * 8;
        aP = (tid & 1) * 4;  aM = tid >> 1;
    } else {
        int m = m0 + (tid & 31) * 4;
        aValid = (m < M);
        aPtr = A + (long long)((tid >> 5) * 2) * p.lda + (aValid ? m : 0);
        aP = tid >> 5;       aM = (tid & 31) * 4;
    }
    bool bValid; const float* bPtr; int bP, bM;
    {
        int n = n0 + (tid & 31) * 4;
        bValid = (n < p.N);
        bPtr = Bp + (long long)((tid >> 5) * 2) * p.ldb + (bValid ? n : 0);
        bP = tid >> 5;       bM = (tid & 31) * 4;
    }

    float acc[4][4][4];
#pragma unroll
    for (int mi = 0; mi < 4; mi++)
#pragma unroll
        for (int ni = 0; ni < 4; ni++)
#pragma unroll
            for (int q = 0; q < 4; q++) acc[mi][ni][q] = 0.f;

    const float4 z4 = make_float4(0.f, 0.f, 0.f, 0.f);
    int kStart = (MODE == 2 && p.causalAV) ? m0 : 0;
    int nIter = (p.K - kStart) >> 4;

    auto loadG = [&](int chunk, float4* fa, float4* fb) {
        int k = kStart + chunk * 16;
        if (MODE != 2) {
            fa[0] = aValid ? *(const float4*)(aPtr + k)     : z4;
            fa[1] = aValid ? *(const float4*)(aPtr + k + 4) : z4;
        } else {
            long long o = (long long)k * p.lda;
            fa[0] = aValid ? *(const float4*)(aPtr + o)          : z4;
            fa[1] = aValid ? *(const float4*)(aPtr + o + p.lda)  : z4;
        }
        long long ob = (long long)k * p.ldb;
        fb[0] = bValid ? *(const float4*)(bPtr + ob)         : z4;
        fb[1] = bValid ? *(const float4*)(bPtr + ob + p.ldb) : z4;
    };
    auto storeS = [&](int buf, const float4* fa, const float4* fb) {
        if (MODE != 2) {
            const float* a8 = (const float*)fa;
#pragma unroll
            for (int j = 0; j < 4; j++)
                sA[buf][aP + j][aM] = split2(a8[2*j] * SC_, a8[2*j+1] * SC_);
        } else {
            const float* r0 = (const float*)&fa[0];
            const float* r1 = (const float*)&fa[1];
#pragma unroll
            for (int j = 0; j < 4; j++)
                sA[buf][aP][aM + j] = split2(r0[j] * SC_, r1[j] * SC_);
        }
        const float* b0 = (const float*)&fb[0];
        const float* b1 = (const float*)&fb[1];
#pragma unroll
        for (int j = 0; j < 4; j++)
            sB[buf][bP][bM + j] = split2(b0[j] * SC_, b1[j] * SC_);
    };

    float4 va[2], vb[2];
    loadG(0, va, vb);
    storeS(0, va, vb);
    __syncthreads();

    for (int it = 0; it < nIter; it++) {
        int cur = it & 1;
        float4 na[2] = {z4, z4}, nb[2] = {z4, z4};
        if (it + 1 < nIter) loadG(it + 1, na, nb);

        uint2 vB0[4], vB1[4];
#pragma unroll
        for (int ni = 0; ni < 4; ni++) {
            int nb2 = wn + ni * 8 + gid;
            vB0[ni] = sB[cur][tg    ][nb2];
            vB1[ni] = sB[cur][tg + 4][nb2];
        }
#pragma unroll
        for (int mi = 0; mi < 4; mi++) {
            int mbb = wm + mi * 16 + gid;
            uint2 a0 = sA[cur][tg    ][mbb];
            uint2 a1 = sA[cur][tg    ][mbb + 8];
            uint2 a2 = sA[cur][tg + 4][mbb];
            uint2 a3 = sA[cur][tg + 4][mbb + 8];
            uint32_t ah[4] = {a0.x, a1.x, a2.x, a3.x};
            uint32_t al[4] = {a0.y, a1.y, a2.y, a3.y};
#pragma unroll
            for (int ni = 0; ni < 4; ni++) {
                uint32_t bh[2] = {vB0[ni].x, vB1[ni].x};
                mma_f16(acc[mi][ni], ah, bh);
            }
#pragma unroll
            for (int ni = 0; ni < 4; ni++) {
                uint32_t bh[2] = {vB0[ni].x, vB1[ni].x};
                mma_f16(acc[mi][ni], al, bh);
            }
#pragma unroll
            for (int ni = 0; ni < 4; ni++) {
                uint32_t bl[2] = {vB0[ni].y, vB1[ni].y};
                mma_f16(acc[mi][ni], ah, bl);
            }
        }

        if (it + 1 < nIter) storeS(cur ^ 1, na, nb);
        __syncthreads();
    }

#pragma unroll
    for (int mi = 0; mi < 4; mi++) {
#pragma unroll
        for (int half = 0; half < 2; half++) {
            int m = m0 + wm + mi * 16 + gid + half * 8;
            if (m >= M) continue;
            long long crow; float w = p.alpha;
            if (p.cRows) {
                crow = (long long)p.cRows[(long long)z * p.cap + m] * p.ldc;
                w *= p.wRow[(long long)z * p.cap + m];
            } else {
                crow = zC + (long long)m * p.ldc;
            }
#pragma unroll
            for (int ni = 0; ni < 4; ni++) {
                int n = n0 + wn + ni * 8 + tg * 2;
                if (n >= p.N) continue;
                float v0 = acc[mi][ni][half * 2 + 0] * w;
                float v1 = acc[mi][ni][half * 2 + 1] * w;
                if (p.cRows) {
                    atomicAdd(&((float*)p.C)[crow + n],     v0);
                    atomicAdd(&((float*)p.C)[crow + n + 1], v1);
                } else if (p.outSplit) {
                    ((uint2*)p.C)[crow + (n >> 1)] = split2(v0 * SC_, v1 * SC_);
                } else {
                    float* Cf = (float*)p.C;
                    if (p.res) { v0 += p.res[crow + n]; v1 += p.res[crow + n + 1]; }
                    Cf[crow + n]     = v0;
                    Cf[crow + n + 1] = v1;
                }
            }
        }
    }
}

// ---------------- producers / small kernels ------------------------------------
__global__ void split_arr_k(const float4* __restrict__ in, uint2* __restrict__ out,
                            long long n4) {
    long long i = (long long)blockIdx.x * 256 + threadIdx.x;
    if (i >= n4) return;
    float4 v = in[i];
    out[2 * i]     = split2(v.x * SC_, v.y * SC_);
    out[2 * i + 1] = split2(v.z * SC_, v.w * SC_);
}

// NN pair pack w/ column stride: out[p*ldout + colOff + n*colStride]
__global__ void split_pack_nn_k(const float* __restrict__ in, uint2* __restrict__ out,
                                long long total, int N, int ldout, int colOff,
                                int colStride) {
    long long i = (long long)blockIdx.x * 256 + threadIdx.x;
    if (i >= total) return;
    long long pr = i / N;
    int n = (int)(i - pr * N);
    out[pr * ldout + colOff + (long long)n * colStride] =
        split2(in[(2 * pr) * N + n] * SC_, in[(2 * pr + 1) * N + n] * SC_);
}

__global__ void reduce_split_k(const float* __restrict__ p0, const float* __restrict__ p1,
                               uint2* __restrict__ out, long long npair) {
    long long i = (long long)blockIdx.x * 256 + threadIdx.x;
    if (i >= npair) return;
    float v0 = p0[2*i]   + p1[2*i];
    float v1 = p0[2*i+1] + p1[2*i+1];
    out[i] = split2(v0 * SC_, v1 * SC_);
}

__global__ void rmsnorm_k(const float* __restrict__ x, const float* __restrict__ w,
                          float* __restrict__ oraw, uint2* __restrict__ osp) {
    int r = blockIdx.x;
    const float* xr = x + (long long)r * DIM_;
    float s = 0.f;
    for (int d = threadIdx.x; d < DIM_; d += 256) { float v = xr[d]; s += v * v; }
    __shared__ float red[256];
    red[threadIdx.x] = s; __syncthreads();
    for (int off = 128; off; off >>= 1) {
        if (threadIdx.x < off) red[threadIdx.x] += red[threadIdx.x + off];
        __syncthreads();
    }
    float inv = rsqrtf(red[0] / (float)DIM_ + 1e-6f);
    for (int pd = threadIdx.x; pd < DIM_/2; pd += 256) {
        int d = pd * 2;
        float v0 = w[d] * xr[d] * inv;
        float v1 = w[d+1] * xr[d+1] * inv;
        if (oraw) { oraw[(long long)r * DIM_ + d] = v0; oraw[(long long)r * DIM_ + d+1] = v1; }
        osp[(long long)r * (DIM_/2) + pd] = split2(v0 * SC_, v1 * SC_);
    }
}

__device__ __forceinline__ void rope_cs(int t, int j, float& c, float& s) {
    float freq = 1.0f / powf(10000.0f, (float)(2 * j) / (float)DRH_);
    float ang = (float)t * freq;
    sincosf(ang, &s, &c);
}
__device__ __forceinline__ void unpack2(uint2 u, float& a, float& b) {
    __half2 h = *(__half2*)&u.x, l = *(__half2*)&u.y;
    a = __low2float(h) + __low2float(l);
    b = __high2float(h) + __high2float(l);
}

__global__ void rope_q_k(uint2* __restrict__ Q) {
    int idx = blockIdx.x;
    int bt = idx / NH_;
    int t = bt % T_;
    int pp = threadIdx.x;
    uint2* base = Q + (long long)idx * (QKD_/2) + DH_/2;
    float re0, re1, im0, im1;
    unpack2(base[pp], re0, re1);
    unpack2(base[16 + pp], im0, im1);
    float c0, s0, c1, s1;
    rope_cs(t, 2*pp, c0, s0); rope_cs(t, 2*pp + 1, c1, s1);
    base[pp]      = split2(re0 * c0 - im0 * s0, re1 * c1 - im1 * s1);
    base[16 + pp] = split2(re0 * s0 + im0 * c0, re1 * s1 + im1 * c1);
}

__global__ void rope_kr_k(const uint2* __restrict__ cdq, uint2* __restrict__ Kb) {
    int bt = blockIdx.x;
    int t = bt % T_;
    int pp = threadIdx.x;
    const uint2* src = cdq + (long long)bt * (NCDQ_/2) + 512;
    float re0, re1, im0, im1;
    unpack2(src[pp], re0, re1);
    unpack2(src[16 + pp], im0, im1);
    float c0, s0, c1, s1;
    rope_cs(t, 2*pp, c0, s0); rope_cs(t, 2*pp + 1, c1, s1);
    float inh = 1.0f / (float)NH_;
    uint2 o1 = split2((re0 * c0 - im0 * s0) * inh, (re1 * c1 - im1 * s1) * inh);
    uint2 o2 = split2((re0 * s0 + im0 * c0) * inh, (re1 * s1 + im1 * c1) * inh);
    for (int h = 0; h < NH_; h++) {
        uint2* base = Kb + ((long long)bt * NH_ + h) * (QKD_/2) + DH_/2;
        base[pp] = o1; base[16 + pp] = o2;
    }
}

__global__ void softmax_k(float* __restrict__ S) {
    long long r = blockIdx.x;
    int t = (int)(r & (T_ - 1));
    float* row = S + r * (long long)T_;
    int n = t + 1;
    int zend = ((t >> 7) + 1) << 7;   // AV only reads cols < end of t's 128-block
    __shared__ float red[256];
    int tid = threadIdx.x;
    float mx = -INFINITY;
    for (int l = tid; l < n; l += 256) mx = fmaxf(mx, row[l]);
    red[tid] = mx; __syncthreads();
    for (int off = 128; off; off >>= 1) {
        if (tid < off) red[tid] = fmaxf(red[tid], red[tid + off]);
        __syncthreads();
    }
    mx = red[0]; __syncthreads();
    float sum = 0.f;
    for (int l = tid; l < n; l += 256) { float e = expf(row[l] - mx); row[l] = e; sum += e; }
    red[tid] = sum; __syncthreads();
    for (int off = 128; off; off >>= 1) {
        if (tid < off) red[tid] += red[tid + off];
        __syncthreads();
    }
    float inv = 1.f / red[0];
    for (int l = tid; l < zend; l += 256) row[l] = (l < n) ? row[l] * inv : 0.f;
}

__global__ void pack_wo_k(const float* __restrict__ wo, uint2* __restrict__ out) {
    long long i = (long long)blockIdx.x * 256 + threadIdx.x;
    if (i >= (long long)DIM_ * 1024) return;
    int d = (int)(i >> 10);
    int pr = (int)(i & 1023);
    int e = pr * 2;
    int h = e >> 7, k = e & 127;
    float s0 = wo[(long long)d * 2048 + k * NH_ + h];
    float s1 = wo[(long long)d * 2048 + (k + 1) * NH_ + h];
    out[i] = split2(s0 * SC_, s1 * SC_);
}

__global__ void gate_k(const float* __restrict__ xn, const float* __restrict__ gw,
                       const float* __restrict__ gb, float* affOut,
                       int* __restrict__ cnt, int* __restrict__ tok,
                       float* __restrict__ wt) {
    int bt = blockIdx.x;
    __shared__ float xrow[DIM_];
    __shared__ float aff[NE_];
    int tid = threadIdx.x;
    for (int d = tid; d < DIM_; d += 256) xrow[d] = xn[(long long)bt * DIM_ + d];
    __syncthreads();
    int w = tid >> 5, lane = tid & 31;
    for (int e = w; e < NE_; e += 8) {
        float s = 0.f;
        const float* gr = gw + (long long)e * DIM_;
        for (int d = lane; d < DIM_; d += 32) s += xrow[d] * gr[d];
        for (int o = 16; o; o >>= 1) s += __shfl_xor_sync(0xffffffffu, s, o);
        if (lane == 0) aff[e] = 1.f / (1.f + expf(-s)) + gb[e];
    }
    __syncthreads();
    if (tid == 0) {
        if (affOut) for (int e = 0; e < NE_; e++) affOut[(long long)bt * NE_ + e] = aff[e];
        bool used[NE_] = {};
        float wv[TOPK_]; int wi[TOPK_]; float sum = 0.f;
        for (int k = 0; k < TOPK_; k++) {
            float best = -1e30f; int bi = 0;
            for (int e = 0; e < NE_; e++)
                if (!used[e] && aff[e] > best) { best = aff[e]; bi = e; }
            used[bi] = true; wv[k] = best; wi[k] = bi; sum += best;
        }
        for (int k = 0; k < TOPK_; k++) {
            int e = wi[k];
            int pos = atomicAdd(&cnt[e], 1);
            tok[e * CAP_ + pos] = bt;
            wt [e * CAP_ + pos] = wv[k] / sum;
        }
    }
}

// ---------------- host helpers ------------------------------------------------
static GemmP mkP(const void* A, const void* B, void* C, int M, int N, int K,
                 int lda, int ldb, int ldc, float alpha, const float* res,
                 int zdiv, long long a1, long long a2, long long b1, long long b2,
                 long long c1, long long c2,
                 const int* Mvec, const int* aRows, const int* cRows,
                 const float* wRow, int cap, int causal, int causalAV, int outSplit,
                 int siluPair = 0) {
    GemmP p;
    p.A = A; p.B = B; p.C = C; p.res = res;
    p.M = M; p.N = N; p.K = K; p.lda = lda; p.ldb = ldb; p.ldc = ldc;
    p.alpha = alpha;
    p.aO1 = a1; p.aO2 = a2; p.bO1 = b1; p.bO2 = b2; p.cO1 = c1; p.cO2 = c2;
    p.zdiv = zdiv; p.cap = cap;
    p.Mvec = Mvec; p.aRows = aRows; p.cRows = cRows; p.wRow = wRow;
    p.causal = causal; p.causalAV = causalAV; p.outSplit = outSplit;
    p.siluPair = siluPair;
    return p;
}

template<int MODE>
static void gemmCA(const uint2* A, const uint2* B, void* C, int M, int N, int K,
                   int ldaP, int ldbP, int ldc, float alpha, const float* res,
                   int nz, int zdiv,
                   long long a1, long long a2, long long b1, long long b2,
                   long long c1, long long c2,
                   int causal = 0, int outSplit = 0,
                   const int* Mvec = nullptr, const int* aRows = nullptr,
                   const int* cRows = nullptr, const float* wRow = nullptr,
                   int cap = 0, int mBlocks = 0, int siluPair = 0) {
    GemmP p = mkP(A, B, C, M, N, K, ldaP, ldbP, ldc, alpha, res, zdiv,
                  a1, a2, b1, b2, c1, c2,
                  Mvec, aRows, cRows, wRow, cap, causal, 0, outSplit, siluPair);
    cudaFuncSetAttribute(gemm_ca<MODE>, cudaFuncAttributeMaxDynamicSharedMemorySize,
                         CA_SMEM_BYTES);
    int gy = mBlocks ? mBlocks : (M + 127) / 128;
    dim3 g((N + 127) / 128, gy, nz);
    gemm_ca<MODE><<<g, 256, CA_SMEM_BYTES>>>(p);
}

template<int MODE>
static void gemmRaw(const float* A, const float* B, void* C, int M, int N, int K,
                    int lda, int ldb, int ldc, float alpha, const float* res,
                    int nz, int zdiv,
                    long long a1, long long a2, long long b1, long long b2,
                    long long c1, long long c2,
                    const int* Mvec = nullptr, const int* aRows = nullptr,
                    const int* cRows = nullptr, const float* wRow = nullptr,
                    int cap = 0, int causalAV = 0, int outSplit = 0) {
    GemmP p = mkP(A, B, C, M, N, K, lda, ldb, ldc, alpha, res, zdiv,
                  a1, a2, b1, b2, c1, c2,
                  Mvec, aRows, cRows, wRow, cap, 0, causalAV, outSplit);
    dim3 g((N + 127) / 128, (M + 127) / 128, nz);
    gemm_k<MODE><<<g, 256>>>(p);
}

static void splitArr(const float* in, uint2* out, long long n) {
    long long n4 = n >> 2;
    split_arr_k<<<(unsigned)((n4 + 255) / 256), 256>>>((const float4*)in, out, n4);
}

extern "C" void kernel_launch(void* const* d_in, const int* in_sizes, int n_in,
                              void* d_out, int out_size) {
    const float* x      = (const float*)d_in[0];
    const float* attn_w = (const float*)d_in[3];
    const float* ffn_w  = (const float*)d_in[4];
    const float* gate_w = (const float*)d_in[5];
    const float* gate_b = (const float*)d_in[6];
    const float* w1s    = (const float*)d_in[7];
    const float* w2s    = (const float*)d_in[8];
    const float* w3s    = (const float*)d_in[9];
    const float* w1r    = (const float*)d_in[10];
    const float* w2r    = (const float*)d_in[11];
    const float* w3r    = (const float*)d_in[12];
    const float* wdkv   = (const float*)d_in[13];
    const float* wuk    = (const float*)d_in[14];
    const float* wuv    = (const float*)d_in[15];
    const float* wdq    = (const float*)d_in[16];
    const float* wuq    = (const float*)d_in[17];
    const float* wqr    = (const float*)d_in[18];
    const float* wkr    = (const float*)d_in[19];
    const float* wo     = (const float*)d_in[20];
    float* out = (float*)d_out;

    float *S, *V, *x1, *xn, *pk, *wt;
    int *cnt, *tok;
    uint2 *h2, *cdq2, *Q2, *K2, *O2, *Wo2, *xn2, *a1s, *h1S;
    uint2 *wA2, *wuk2, *wuv2, *wuq2, *wqr2, *w13s2, *w2s2, *w13r2, *w2r2;
    cudaGetSymbolAddress((void**)&S,   g_S);
    cudaGetSymbolAddress((void**)&V,   g_V);
    cudaGetSymbolAddress((void**)&x1,  g_x1);
    cudaGetSymbolAddress((void**)&xn,  g_xn);
    cudaGetSymbolAddress((void**)&pk,  g_pk);
    cudaGetSymbolAddress((void**)&cnt, g_cnt);
    cudaGetSymbolAddress((void**)&tok, g_tok);
    cudaGetSymbolAddress((void**)&wt,  g_wt);
    cudaGetSymbolAddress((void**)&h2,  g_h2);
    cudaGetSymbolAddress((void**)&cdq2, g_cdq2);
    cudaGetSymbolAddress((void**)&Q2,  g_Q2);
    cudaGetSymbolAddress((void**)&K2,  g_K2);
    cudaGetSymbolAddress((void**)&O2,  g_O2);
    cudaGetSymbolAddress((void**)&Wo2, g_Wo2);
    cudaGetSymbolAddress((void**)&xn2, g_xn2);
    cudaGetSymbolAddress((void**)&a1s, g_a1s);
    cudaGetSymbolAddress((void**)&h1S, g_h1S);
    cudaGetSymbolAddress((void**)&wA2,  g_wA2);
    cudaGetSymbolAddress((void**)&wuk2, g_wuk2);
    cudaGetSymbolAddress((void**)&wuv2, g_wuv2);
    cudaGetSymbolAddress((void**)&wuq2, g_wuq2);
    cudaGetSymbolAddress((void**)&wqr2, g_wqr2);
    cudaGetSymbolAddress((void**)&w13s2, g_w13s2);
    cudaGetSymbolAddress((void**)&w2s2,  g_w2s2);
    cudaGetSymbolAddress((void**)&w13r2, g_w13r2);
    cudaGetSymbolAddress((void**)&w2r2,  g_w2r2);

    // ---- weight pre-split / packing ----
    splitArr(wdkv, wA2,                           (long long)DC_*DIM_);
    splitArr(wdq,  wA2 + (long long)DC_*DIM_/2,   (long long)DC_*DIM_);
    splitArr(wkr,  wA2 + (long long)DC_*DIM_,     (long long)DRH_*DIM_);
    splitArr(wuk,  wuk2, (long long)DH_*NH_*DC_);
    splitArr(wuv,  wuv2, (long long)DH_*NH_*DC_);
    splitArr(wuq,  wuq2, (long long)DH_*NH_*DC_);
    splitArr(wqr,  wqr2, (long long)DRH_*NH_*DC_);
    {   // shared FFN: w1/w3 interleaved columns for fused-silu epilogue
        long long tot = (long long)(DIM_/2) * MOESH_;
        unsigned nb = (unsigned)((tot + 255) / 256);
        split_pack_nn_k<<<nb, 256>>>(w1s, w13s2, tot, MOESH_, 2*MOESH_, 0, 2);
        split_pack_nn_k<<<nb, 256>>>(w3s, w13s2, tot, MOESH_, 2*MOESH_, 1, 2);
        long long tot2 = (long long)(MOESH_/2) * DIM_;
        split_pack_nn_k<<<(unsigned)((tot2 + 255)/256), 256>>>(w2s, w2s2, tot2, DIM_, DIM_, 0, 1);
    }
    {   // routed: interleaved w1r/w3r
        long long totr = (long long)NE_ * (DIM_/2) * MOE_;
        unsigned nbr = (unsigned)((totr + 255) / 256);
        split_pack_nn_k<<<nbr, 256>>>(w1r, w13r2, totr, MOE_, 2*MOE_, 0, 2);
        split_pack_nn_k<<<nbr, 256>>>(w3r, w13r2, totr, MOE_, 2*MOE_, 1, 2);
        long long totr2 = (long long)NE_ * (MOE_/2) * DIM_;
        split_pack_nn_k<<<(unsigned)((totr2 + 255)/256), 256>>>(w2r, w2r2, totr2, DIM_, DIM_, 0, 1);
    }
    pack_wo_k<<<(unsigned)(((long long)DIM_*1024 + 255)/256), 256>>>(wo, Wo2);

    // ---- attention ----
    rmsnorm_k<<<BT_, 256>>>(x, attn_w, nullptr, h2);
    gemmCA<1>(h2, wA2, pk, BT_, NCDQ_, DIM_/2, DIM_/2, DIM_/2, NCDQ_, ASC_, nullptr,
              2, 1, /*aO1=*/DIM_/4, 0, /*bO1=*/DIM_/4, 0,
              /*cO1=*/(long long)BT_*NCDQ_, 0, 0, 0);
    {
        long long np = (long long)BT_*NCDQ_/2;
        reduce_split_k<<<(unsigned)((np + 255)/256), 256>>>(pk, pk + (long long)BT_*NCDQ_, cdq2, np);
    }
    gemmCA<1>(cdq2, wuk2, K2, BT_, DH_, DC_, NCDQ_/2, NH_*DC_/2, NH_*QKD_/2, ASC_, nullptr,
              NH_, NH_, 0,0, 0, DC_/2, 0, QKD_/2, 0, 1);
    gemmCA<1>(cdq2, wuv2, (void*)V, BT_, DH_, DC_, NCDQ_/2, NH_*DC_/2, NH_*DH_, ASC_, nullptr,
              NH_, NH_, 0,0, 0, DC_/2, 0, DH_, 0, 0);
    gemmCA<1>(cdq2 + DC_/2, wuq2, Q2, BT_, DH_, DC_, NCDQ_/2, NH_*DC_/2, NH_*QKD_/2,
              ASC_, nullptr, NH_, NH_, 0,0, 0, DC_/2, 0, QKD_/2, 0, 1);
    gemmCA<1>(cdq2 + DC_/2, wqr2, Q2 + DH_/2, BT_, DRH_, DC_, NCDQ_/2, NH_*DC_/2, NH_*QKD_/2,
              ASC_, nullptr, NH_, NH_, 0,0, 0, DC_/2, 0, QKD_/2, 0, 1);
    rope_q_k<<<BT_ * NH_, 16>>>(Q2);
    rope_kr_k<<<BT_, 16>>>(cdq2, K2);
    float scale = ASC_ / sqrtf((float)QKD_);
    gemmCA<1>(Q2, K2, S, T_, T_, QKD_, NH_*QKD_/2, NH_*QKD_/2, T_, scale, nullptr,
              B_*NH_, NH_,
              (long long)T_*NH_*QKD_/2, QKD_/2,
              (long long)T_*NH_*QKD_/2, QKD_/2,
              (long long)NH_*T_*T_, (long long)T_*T_,
              /*causal=*/1, 0);
    softmax_k<<<B_ * NH_ * T_, 256>>>(S);
    gemmRaw<2>(S, V, O2, T_, DH_, T_, T_, NH_*DH_, NH_*DH_/2, ASC_, nullptr,
               B_*NH_, NH_,
               (long long)NH_*T_*T_, (long long)T_*T_,
               (long long)T_*NH_*DH_, DH_,
               (long long)T_*NH_*DH_/2, DH_/2,
               nullptr, nullptr, nullptr, nullptr, 0, /*causalAV=*/1, /*outSplit=*/1);
    gemmCA<1>(O2, Wo2, x1, BT_, DIM_, NH_*DH_, NH_*DH_/2, NH_*DH_/2, DIM_, ASC_, x,
              1, 1, 0,0,0,0,0,0, 0, 0);

    // ---- MoE ----
    rmsnorm_k<<<BT_, 256>>>(x1, ffn_w, xn, xn2);
    cudaMemsetAsync(cnt, 0, NE_ * sizeof(int));
    float* affOut = (out_size >= BT_*DIM_ + BT_*NE_) ? out + (long long)BT_*DIM_ : nullptr;
    gate_k<<<BT_, 256>>>(xn, gate_w, gate_b, affOut, cnt, tok, wt);
    // shared FFN up + fused silu -> a1s pairs (ldc in pair units = MOESH/2)
    gemmCA<0>(xn2, w13s2, a1s, BT_, 2*MOESH_, DIM_, DIM_/2, 2*MOESH_, MOESH_/2, ASC_, nullptr,
              1, 1, 0,0,0,0,0,0, 0, 0,
              nullptr, nullptr, nullptr, nullptr, 0, 0, /*siluPair=*/1);
    // shared FFN down (identical to R14)
    gemmCA<0>(a1s, w2s2, out, BT_, DIM_, MOESH_, MOESH_/2, DIM_, DIM_, ASC_, x1,
              1, 1, 0,0,0,0,0,0, 0, 0);
    // routed up + fused silu -> h1S pairs (ldc = MOE/2)
    gemmCA<0>(xn2, w13r2, h1S, CAP_, 2*MOE_, DIM_, DIM_/2, 2*MOE_, MOE_/2, ASC_, nullptr,
              NE_, NE_, 0,0, 0, (long long)(DIM_/2)*2*MOE_, 0, (long long)CAP_*(MOE_/2),
              0, 0, cnt, tok, nullptr, nullptr, CAP_, CAP_/128, /*siluPair=*/1);
    // routed down (identical to R14), weighted atomic scatter
    gemmCA<0>(h1S, w2r2, out, CAP_, DIM_, MOE_, MOE_/2, DIM_, DIM_, ASC_, nullptr,
              NE_, NE_, 0, (long long)CAP_*(MOE_/2), 0, (long long)(MOE_/2)*DIM_, 0, 0,
              0, 0, cnt, nullptr, tok, wt, CAP_, CAP_/128);
}

// round 17
// speedup vs baseline: 1.0571x; 1.0365x over previous
#include <cuda_runtime.h>
#include <cuda_fp16.h>
#include <math.h>
#include <stdint.h>

#define B_    2
#define T_    1024
#define BT_   2048
#define DIM_  2048
#define NH_   16
#define DH_   128
#define DRH_  64
#define DC_   512
#define NE_   16
#define TOPK_ 4
#define MOE_  1024
#define MOESH_ 2048
#define CAP_  2048
#define QKD_  192
#define NCDQ_ 1088
#define SC_   256.0f
#define ASC_  (1.0f/65536.0f)

// ---------------- scratch ----------------
__device__ float g_S  [(size_t)B_*NH_*T_*T_];
__device__ float g_V  [BT_*NH_*DH_];
__device__ float g_x1 [BT_*DIM_];
__device__ float g_xn [BT_*DIM_];
__device__ float g_a13[(size_t)BT_*2*MOESH_];
__device__ float g_h12[(size_t)NE_*CAP_*2*MOE_];
__device__ float g_pk [2][(size_t)BT_*NCDQ_];
__device__ int   g_cnt[NE_];
__device__ int   g_tok[NE_*CAP_];
__device__ float g_wt [NE_*CAP_];
// fp16 pair-split buffers (uint2 = (hi2,lo2) of k,k+1), values x*256
__device__ __align__(16) uint2 g_h2  [BT_*DIM_/2];
__device__ __align__(16) uint2 g_cdq2[(size_t)BT_*NCDQ_/2];
__device__ __align__(16) uint2 g_Q2  [BT_*NH_*QKD_/2];
__device__ __align__(16) uint2 g_K2  [BT_*NH_*QKD_/2];
__device__ __align__(16) uint2 g_O2  [BT_*NH_*DH_/2];
__device__ __align__(16) uint2 g_Wo2 [(size_t)DIM_*NH_*DH_/2];
__device__ __align__(16) uint2 g_xn2 [BT_*DIM_/2];
__device__ __align__(16) uint2 g_a1s [BT_*MOESH_/2];
__device__ __align__(16) uint2 g_h1S [(size_t)NE_*CAP_*MOE_/2];
// split weights
__device__ __align__(16) uint2 g_wA2  [(size_t)NCDQ_*DIM_/2];
__device__ __align__(16) uint2 g_wuk2 [DH_*NH_*DC_/2];
__device__ __align__(16) uint2 g_wuv2 [DH_*NH_*DC_/2];
__device__ __align__(16) uint2 g_wuq2 [DH_*NH_*DC_/2];
__device__ __align__(16) uint2 g_wqr2 [DRH_*NH_*DC_/2];
__device__ __align__(16) uint2 g_w13s2[(size_t)(DIM_/2)*2*MOESH_];
__device__ __align__(16) uint2 g_w2s2 [(size_t)(MOESH_/2)*DIM_];
__device__ __align__(16) uint2 g_w13r2[(size_t)NE_*(DIM_/2)*2*MOE_];
__device__ __align__(16) uint2 g_w2r2 [(size_t)NE_*(MOE_/2)*DIM_];

__device__ __forceinline__ uint2 split2(float x, float y) {
    __half hx = __float2half_rn(x), hy = __float2half_rn(y);
    float lx = x - __half2float(hx), ly = y - __half2float(hy);
    __half2 h = __halves2half2(hx, hy);
    __half2 l = __halves2half2(__float2half_rn(lx), __float2half_rn(ly));
    uint2 r; r.x = *(uint32_t*)&h; r.y = *(uint32_t*)&l;
    return r;
}
__device__ __forceinline__ void mma_f16(float* c, const uint32_t* a, const uint32_t* b) {
    asm volatile("mma.sync.aligned.m16n8k16.row.col.f32.f16.f16.f32 "
        "{%0,%1,%2,%3}, {%4,%5,%6,%7}, {%8,%9}, {%0,%1,%2,%3};\n"
        : "+f"(c[0]), "+f"(c[1]), "+f"(c[2]), "+f"(c[3])
        : "r"(a[0]), "r"(a[1]), "r"(a[2]), "r"(a[3]), "r"(b[0]), "r"(b[1]));
}

struct GemmP {
    const void* A; const void* B; void* C; const float* res;
    int M, N, K, lda, ldb, ldc;   // lda/ldb: PAIR strides for split ops; floats for raw
    float alpha;
    long long aO1, aO2, bO1, bO2, cO1, cO2;
    int zdiv, cap;
    const int* Mvec; const int* aRows; const int* cRows; const float* wRow;
    int causal, causalAV, outSplit;
};

// ============ cp.async GEMM (pair-split operands) ==============================
// MODE 0: B NN pair-packed [K/2][N]; MODE 1: B NT [N][K/2]. A always [M][K/2].
// Supports gathered A rows (aRows), dynamic M (Mvec), atomic scatter (cRows/wRow).
#define CA_STAGE_U2 2112
#define CA_SMEM_BYTES (4 * CA_STAGE_U2 * 8)

__device__ __forceinline__ void cp_async8(uint32_t saddr, const void* gaddr, int sz) {
    asm volatile("cp.async.ca.shared.global [%0], [%1], 8, %2;"
                 :: "r"(saddr), "l"(gaddr), "r"(sz) : "memory");
}

template<int MODE>
__global__ __launch_bounds__(256, 2) void gemm_ca(GemmP p) {
    extern __shared__ uint2 dyn[];
    uint32_t smemBase = (uint32_t)__cvta_generic_to_shared(dyn);

    int z = blockIdx.z, z1 = z / p.zdiv, z2 = z - z1 * p.zdiv;
    long long zA = z1 * p.aO1 + z2 * p.aO2;
    long long zB = z1 * p.bO1 + z2 * p.bO2;
    long long zC = z1 * p.cO1 + z2 * p.cO2;
    int M = p.Mvec ? p.Mvec[z] : p.M;
    int m0 = blockIdx.y * 128, n0 = blockIdx.x * 128;
    if (m0 >= M) return;
    if (MODE == 1 && p.causal && n0 >= m0 + 128) return;
    int tid = threadIdx.x, lane = tid & 31, warp = tid >> 5;
    int wm = (warp & 1) << 6, wn = (warp >> 1) << 5;
    int gid = lane >> 2, tg = lane & 3;

    long long gA[4]; uint32_t sAoff[4]; int szA[4];
    long long gB[4]; uint32_t sBoff[4]; int szB[4];
    long long strideB = (MODE == 1) ? 8 : (long long)8 * p.ldb;
#pragma unroll
    for (int i = 0; i < 4; i++) {
        int e = tid + 256 * i;
        int am = e >> 3, ak = e & 7;
        int row = m0 + am;
        bool va = row < M;
        long long ar = 0;
        if (va) ar = p.aRows ? (long long)p.aRows[(long long)z * p.cap + row]
                             : (long long)row;
        gA[i] = zA + ar * p.lda + ak;
        sAoff[i] = (uint32_t)(ak * 132 + am) * 8;
        szA[i] = va ? 8 : 0;
        if (MODE == 1) {
            int bn = e >> 3, bk = e & 7;
            bool vb = (n0 + bn) < p.N;
            gB[i] = zB + (long long)(vb ? (n0 + bn) : 0) * p.ldb + bk;
            sBoff[i] = (uint32_t)(1056 + bk * 132 + bn) * 8;
            szB[i] = vb ? 8 : 0;
        } else {
            int bk = e >> 7, bn = e & 127;
            bool vb = (n0 + bn) < p.N;
            gB[i] = zB + (long long)bk * p.ldb + n0 + (vb ? bn : 0);
            sBoff[i] = (uint32_t)(1056 + bk * 132 + bn) * 8;
            szB[i] = vb ? 8 : 0;
        }
    }

    float acc[4][4][4];
#pragma unroll
    for (int mi = 0; mi < 4; mi++)
#pragma unroll
        for (int ni = 0; ni < 4; ni++)
#pragma unroll
            for (int q = 0; q < 4; q++) acc[mi][ni][q] = 0.f;

    int nIter = p.K >> 4;
    const uint2* Ag = (const uint2*)p.A;
    const uint2* Bg = (const uint2*)p.B;

    auto issue = [&](int stage, int chunk) {
        uint32_t base = smemBase + (uint32_t)stage * CA_STAGE_U2 * 8;
        long long ka = (long long)chunk * 8;
        long long kb = (long long)chunk * strideB;
#pragma unroll
        for (int i = 0; i < 4; i++)
            cp_async8(base + sAoff[i], Ag + gA[i] + ka, szA[i]);
#pragma unroll
        for (int i = 0; i < 4; i++)
            cp_async8(base + sBoff[i], Bg + gB[i] + kb, szB[i]);
    };

#pragma unroll
    for (int s = 0; s < 3; s++) {
        if (s < nIter) issue(s, s);
        asm volatile("cp.async.commit_group;" ::: "memory");
    }

    for (int it = 0; it < nIter; it++) {
        asm volatile("cp.async.wait_group 2;" ::: "memory");
        __syncthreads();
        if (it + 3 < nIter) issue((it + 3) & 3, it + 3);
        asm volatile("cp.async.commit_group;" ::: "memory");

        const uint2* sA = dyn + (it & 3) * CA_STAGE_U2;
        const uint2* sB = sA + 1056;
        uint2 vB0[4], vB1[4];
#pragma unroll
        for (int ni = 0; ni < 4; ni++) {
            int nb2 = wn + ni * 8 + gid;
            vB0[ni] = sB[tg * 132 + nb2];
            vB1[ni] = sB[(tg + 4) * 132 + nb2];
        }
#pragma unroll
        for (int mi = 0; mi < 4; mi++) {
            int mb = wm + mi * 16 + gid;
            uint2 a0 = sA[tg * 132 + mb];
            uint2 a1 = sA[tg * 132 + mb + 8];
            uint2 a2 = sA[(tg + 4) * 132 + mb];
            uint2 a3 = sA[(tg + 4) * 132 + mb + 8];
            uint32_t ah[4] = {a0.x, a1.x, a2.x, a3.x};
            uint32_t al[4] = {a0.y, a1.y, a2.y, a3.y};
#pragma unroll
            for (int ni = 0; ni < 4; ni++) {
                uint32_t bh[2] = {vB0[ni].x, vB1[ni].x};
                mma_f16(acc[mi][ni], ah, bh);
            }
#pragma unroll
            for (int ni = 0; ni < 4; ni++) {
                uint32_t bh[2] = {vB0[ni].x, vB1[ni].x};
                mma_f16(acc[mi][ni], al, bh);
            }
#pragma unroll
            for (int ni = 0; ni < 4; ni++) {
                uint32_t bl[2] = {vB0[ni].y, vB1[ni].y};
                mma_f16(acc[mi][ni], ah, bl);
            }
        }
    }

#pragma unroll
    for (int mi = 0; mi < 4; mi++) {
#pragma unroll
        for (int half = 0; half < 2; half++) {
            int m = m0 + wm + mi * 16 + gid + half * 8;
            if (m >= M) continue;
            long long crow; float w = p.alpha;
            if (p.cRows) {
                crow = (long long)p.cRows[(long long)z * p.cap + m] * p.ldc;
                w *= p.wRow[(long long)z * p.cap + m];
            } else {
                crow = zC + (long long)m * p.ldc;
            }
#pragma unroll
            for (int ni = 0; ni < 4; ni++) {
                int n = n0 + wn + ni * 8 + tg * 2;
                if (n >= p.N) continue;
                float v0 = acc[mi][ni][half * 2 + 0] * w;
                float v1 = acc[mi][ni][half * 2 + 1] * w;
                if (p.cRows) {
                    atomicAdd(&((float*)p.C)[crow + n],     v0);
                    atomicAdd(&((float*)p.C)[crow + n + 1], v1);
                } else if (p.outSplit) {
                    ((uint2*)p.C)[crow + (n >> 1)] = split2(v0 * SC_, v1 * SC_);
                } else {
                    float* Cf = (float*)p.C;
                    if (p.res) { v0 += p.res[crow + n]; v1 += p.res[crow + n + 1]; }
                    Cf[crow + n]     = v0;
                    Cf[crow + n + 1] = v1;
                }
            }
        }
    }
}

// ============ raw mma.sync GEMM (fp16-split in loop) — AV only =================
template<int MODE>
__global__ __launch_bounds__(256, 2) void gemm_k(GemmP p) {
    __shared__ uint2 sA[2][8][132];
    __shared__ uint2 sB[2][8][132];

    int z = blockIdx.z, z1 = z / p.zdiv, z2 = z - z1 * p.zdiv;
    const float* A  = (const float*)p.A + z1 * p.aO1 + z2 * p.aO2;
    const float* Bp = (const float*)p.B + z1 * p.bO1 + z2 * p.bO2;
    long long zC = z1 * p.cO1 + z2 * p.cO2;
    int M = p.Mvec ? p.Mvec[z] : p.M;
    int m0 = blockIdx.y * 128, n0 = blockIdx.x * 128;
    if (m0 >= M) return;
    int tid = threadIdx.x, lane = tid & 31, warp = tid >> 5;
    int wm = (warp & 1) << 6, wn = (warp >> 1) << 5;
    int gid = lane >> 2, tg = lane & 3;

    bool aValid; const float* aPtr; int aP, aM;
    if (MODE != 2) {
        int r = m0 + (tid >> 1);
        aValid = (r < M);
        long long ar = 0;
        if (aValid) ar = p.aRows ? (long long)p.aRows[(long long)z * p.cap + r]
                                 : (long long)r;
        aPtr = A + ar * (long long)p.lda + (tid & 1) * 8;
        aP = (tid & 1) * 4;  aM = tid >> 1;
    } else {
        int m = m0 + (tid & 31) * 4;
        aValid = (m < M);
        aPtr = A + (long long)((tid >> 5) * 2) * p.lda + (aValid ? m : 0);
        aP = tid >> 5;       aM = (tid & 31) * 4;
    }
    bool bValid; const float* bPtr; int bP, bM;
    {
        int n = n0 + (tid & 31) * 4;
        bValid = (n < p.N);
        bPtr = Bp + (long long)((tid >> 5) * 2) * p.ldb + (bValid ? n : 0);
        bP = tid >> 5;       bM = (tid & 31) * 4;
    }

    float acc[4][4][4];
#pragma unroll
    for (int mi = 0; mi < 4; mi++)
#pragma unroll
        for (int ni = 0; ni < 4; ni++)
#pragma unroll
            for (int q = 0; q < 4; q++) acc[mi][ni][q] = 0.f;

    const float4 z4 = make_float4(0.f, 0.f, 0.f, 0.f);
    int kStart = (MODE == 2 && p.causalAV) ? m0 : 0;
    int nIter = (p.K - kStart) >> 4;

    auto loadG = [&](int chunk, float4* fa, float4* fb) {
        int k = kStart + chunk * 16;
        if (MODE != 2) {
            fa[0] = aValid ? *(const float4*)(aPtr + k)     : z4;
            fa[1] = aValid ? *(const float4*)(aPtr + k + 4) : z4;
        } else {
            long long o = (long long)k * p.lda;
            fa[0] = aValid ? *(const float4*)(aPtr + o)          : z4;
            fa[1] = aValid ? *(const float4*)(aPtr + o + p.lda)  : z4;
        }
        long long ob = (long long)k * p.ldb;
        fb[0] = bValid ? *(const float4*)(bPtr + ob)         : z4;
        fb[1] = bValid ? *(const float4*)(bPtr + ob + p.ldb) : z4;
    };
    auto storeS = [&](int buf, const float4* fa, const float4* fb) {
        if (MODE != 2) {
            const float* a8 = (const float*)fa;
#pragma unroll
            for (int j = 0; j < 4; j++)
                sA[buf][aP + j][aM] = split2(a8[2*j] * SC_, a8[2*j+1] * SC_);
        } else {
            const float* r0 = (const float*)&fa[0];
            const float* r1 = (const float*)&fa[1];
#pragma unroll
            for (int j = 0; j < 4; j++)
                sA[buf][aP][aM + j] = split2(r0[j] * SC_, r1[j] * SC_);
        }
        const float* b0 = (const float*)&fb[0];
        const float* b1 = (const float*)&fb[1];
#pragma unroll
        for (int j = 0; j < 4; j++)
            sB[buf][bP][bM + j] = split2(b0[j] * SC_, b1[j] * SC_);
    };

    float4 va[2], vb[2];
    loadG(0, va, vb);
    storeS(0, va, vb);
    __syncthreads();

    for (int it = 0; it < nIter; it++) {
        int cur = it & 1;
        float4 na[2] = {z4, z4}, nb[2] = {z4, z4};
        if (it + 1 < nIter) loadG(it + 1, na, nb);

        uint2 vB0[4], vB1[4];
#pragma unroll
        for (int ni = 0; ni < 4; ni++) {
            int nb2 = wn + ni * 8 + gid;
            vB0[ni] = sB[cur][tg    ][nb2];
            vB1[ni] = sB[cur][tg + 4][nb2];
        }
#pragma unroll
        for (int mi = 0; mi < 4; mi++) {
            int mbb = wm + mi * 16 + gid;
            uint2 a0 = sA[cur][tg    ][mbb];
            uint2 a1 = sA[cur][tg    ][mbb + 8];
            uint2 a2 = sA[cur][tg + 4][mbb];
            uint2 a3 = sA[cur][tg + 4][mbb + 8];
            uint32_t ah[4] = {a0.x, a1.x, a2.x, a3.x};
            uint32_t al[4] = {a0.y, a1.y, a2.y, a3.y};
#pragma unroll
            for (int ni = 0; ni < 4; ni++) {
                uint32_t bh[2] = {vB0[ni].x, vB1[ni].x};
                mma_f16(acc[mi][ni], ah, bh);
            }
#pragma unroll
            for (int ni = 0; ni < 4; ni++) {
                uint32_t bh[2] = {vB0[ni].x, vB1[ni].x};
                mma_f16(acc[mi][ni], al, bh);
            }
#pragma unroll
            for (int ni = 0; ni < 4; ni++) {
                uint32_t bl[2] = {vB0[ni].y, vB1[ni].y};
                mma_f16(acc[mi][ni], ah, bl);
            }
        }

        if (it + 1 < nIter) storeS(cur ^ 1, na, nb);
        __syncthreads();
    }

#pragma unroll
    for (int mi = 0; mi < 4; mi++) {
#pragma unroll
        for (int half = 0; half < 2; half++) {
            int m = m0 + wm + mi * 16 + gid + half * 8;
            if (m >= M) continue;
            long long crow; float w = p.alpha;
            if (p.cRows) {
                crow = (long long)p.cRows[(long long)z * p.cap + m] * p.ldc;
                w *= p.wRow[(long long)z * p.cap + m];
            } else {
                crow = zC + (long long)m * p.ldc;
            }
#pragma unroll
            for (int ni = 0; ni < 4; ni++) {
                int n = n0 + wn + ni * 8 + tg * 2;
                if (n >= p.N) continue;
                float v0 = acc[mi][ni][half * 2 + 0] * w;
                float v1 = acc[mi][ni][half * 2 + 1] * w;
                if (p.cRows) {
                    atomicAdd(&((float*)p.C)[crow + n],     v0);
                    atomicAdd(&((float*)p.C)[crow + n + 1], v1);
                } else if (p.outSplit) {
                    ((uint2*)p.C)[crow + (n >> 1)] = split2(v0 * SC_, v1 * SC_);
                } else {
                    float* Cf = (float*)p.C;
                    if (p.res) { v0 += p.res[crow + n]; v1 += p.res[crow + n + 1]; }
                    Cf[crow + n]     = v0;
                    Cf[crow + n + 1] = v1;
                }
            }
        }
    }
}

// ---------------- producers / small kernels ------------------------------------
__global__ void split_arr_k(const float4* __restrict__ in, uint2* __restrict__ out,
                            long long n4) {
    long long i = (long long)blockIdx.x * 256 + threadIdx.x;
    if (i >= n4) return;
    float4 v = in[i];
    out[2 * i]     = split2(v.x * SC_, v.y * SC_);
    out[2 * i + 1] = split2(v.z * SC_, v.w * SC_);
}

// NN pair pack: out[p*ldout + colOff + n] = split2(in[2p][n], in[2p+1][n])
__global__ void split_pack_nn_k(const float* __restrict__ in, uint2* __restrict__ out,
                                long long total, int N, int ldout, int colOff) {
    long long i = (long long)blockIdx.x * 256 + threadIdx.x;
    if (i >= total) return;
    long long pr = i / N;
    int n = (int)(i - pr * N);
    out[pr * ldout + colOff + n] =
        split2(in[(2 * pr) * N + n] * SC_, in[(2 * pr + 1) * N + n] * SC_);
}

__global__ void reduce_split_k(const float* __restrict__ p0, const float* __restrict__ p1,
                               uint2* __restrict__ out, long long npair) {
    long long i = (long long)blockIdx.x * 256 + threadIdx.x;
    if (i >= npair) return;
    float v0 = p0[2*i]   + p1[2*i];
    float v1 = p0[2*i+1] + p1[2*i+1];
    out[i] = split2(v0 * SC_, v1 * SC_);
}

__global__ void rmsnorm_k(const float* __restrict__ x, const float* __restrict__ w,
                          float* __restrict__ oraw, uint2* __restrict__ osp) {
    int r = blockIdx.x;
    const float* xr = x + (long long)r * DIM_;
    float s = 0.f;
    for (int d = threadIdx.x; d < DIM_; d += 256) { float v = xr[d]; s += v * v; }
    __shared__ float red[256];
    red[threadIdx.x] = s; __syncthreads();
    for (int off = 128; off; off >>= 1) {
        if (threadIdx.x < off) red[threadIdx.x] += red[threadIdx.x + off];
        __syncthreads();
    }
    float inv = rsqrtf(red[0] / (float)DIM_ + 1e-6f);
    for (int pd = threadIdx.x; pd < DIM_/2; pd += 256) {
        int d = pd * 2;
        float v0 = w[d] * xr[d] * inv;
        float v1 = w[d+1] * xr[d+1] * inv;
        if (oraw) { oraw[(long long)r * DIM_ + d] = v0; oraw[(long long)r * DIM_ + d+1] = v1; }
        osp[(long long)r * (DIM_/2) + pd] = split2(v0 * SC_, v1 * SC_);
    }
}

__device__ __forceinline__ void rope_cs(int t, int j, float& c, float& s) {
    float freq = 1.0f / powf(10000.0f, (float)(2 * j) / (float)DRH_);
    float ang = (float)t * freq;
    sincosf(ang, &s, &c);
}
__device__ __forceinline__ void unpack2(uint2 u, float& a, float& b) {
    __half2 h = *(__half2*)&u.x, l = *(__half2*)&u.y;
    a = __low2float(h) + __low2float(l);
    b = __high2float(h) + __high2float(l);
}

__global__ void rope_q_k(uint2* __restrict__ Q) {   // 16 threads
    int idx = blockIdx.x;
    int bt = idx / NH_;
    int t = bt % T_;
    int pp = threadIdx.x;
    uint2* base = Q + (long long)idx * (QKD_/2) + DH_/2;
    float re0, re1, im0, im1;
    unpack2(base[pp], re0, re1);
    unpack2(base[16 + pp], im0, im1);
    float c0, s0, c1, s1;
    rope_cs(t, 2*pp, c0, s0); rope_cs(t, 2*pp + 1, c1, s1);
    base[pp]      = split2(re0 * c0 - im0 * s0, re1 * c1 - im1 * s1);
    base[16 + pp] = split2(re0 * s0 + im0 * c0, re1 * s1 + im1 * c1);
}

__global__ void rope_kr_k(const uint2* __restrict__ cdq, uint2* __restrict__ Kb) {
    int bt = blockIdx.x;
    int t = bt % T_;
    int pp = threadIdx.x;
    const uint2* src = cdq + (long long)bt * (NCDQ_/2) + 512;
    float re0, re1, im0, im1;
    unpack2(src[pp], re0, re1);
    unpack2(src[16 + pp], im0, im1);
    float c0, s0, c1, s1;
    rope_cs(t, 2*pp, c0, s0); rope_cs(t, 2*pp + 1, c1, s1);
    float inh = 1.0f / (float)NH_;
    uint2 o1 = split2((re0 * c0 - im0 * s0) * inh, (re1 * c1 - im1 * s1) * inh);
    uint2 o2 = split2((re0 * s0 + im0 * c0) * inh, (re1 * s1 + im1 * c1) * inh);
    for (int h = 0; h < NH_; h++) {
        uint2* base = Kb + ((long long)bt * NH_ + h) * (QKD_/2) + DH_/2;
        base[pp] = o1; base[16 + pp] = o2;
    }
}

__global__ void softmax_k(float* __restrict__ S) {
    long long r = blockIdx.x;
    int t = (int)(r & (T_ - 1));
    float* row = S + r * (long long)T_;
    int n = t + 1;
    int zend = ((t >> 7) + 1) << 7;   // AV reads only cols < end of t's 128-block
    __shared__ float red[256];
    int tid = threadIdx.x;
    float mx = -INFINITY;
    for (int l = tid; l < n; l += 256) mx = fmaxf(mx, row[l]);
    red[tid] = mx; __syncthreads();
    for (int off = 128; off; off >>= 1) {
        if (tid < off) red[tid] = fmaxf(red[tid], red[tid + off]);
        __syncthreads();
    }
    mx = red[0]; __syncthreads();
    float sum = 0.f;
    for (int l = tid; l < n; l += 256) { float e = expf(row[l] - mx); row[l] = e; sum += e; }
    red[tid] = sum; __syncthreads();
    for (int off = 128; off; off >>= 1) {
        if (tid < off) red[tid] += red[tid + off];
        __syncthreads();
    }
    float inv = 1.f / red[0];
    for (int l = tid; l < zend; l += 256) row[l] = (l < n) ? row[l] * inv : 0.f;
}

__global__ void pack_wo_k(const float* __restrict__ wo, uint2* __restrict__ out) {
    long long i = (long long)blockIdx.x * 256 + threadIdx.x;
    if (i >= (long long)DIM_ * 1024) return;
    int d = (int)(i >> 10);
    int pr = (int)(i & 1023);
    int e = pr * 2;
    int h = e >> 7, k = e & 127;
    float s0 = wo[(long long)d * 2048 + k * NH_ + h];
    float s1 = wo[(long long)d * 2048 + (k + 1) * NH_ + h];
    out[i] = split2(s0 * SC_, s1 * SC_);
}

__global__ void gate_k(const float* __restrict__ xn, const float* __restrict__ gw,
                       const float* __restrict__ gb, float* affOut,
                       int* __restrict__ cnt, int* __restrict__ tok,
                       float* __restrict__ wt) {
    int bt = blockIdx.x;
    __shared__ float xrow[DIM_];
    __shared__ float aff[NE_];
    int tid = threadIdx.x;
    for (int d = tid; d < DIM_; d += 256) xrow[d] = xn[(long long)bt * DIM_ + d];
    __syncthreads();
    int w = tid >> 5, lane = tid & 31;
    for (int e = w; e < NE_; e += 8) {
        float s = 0.f;
        const float* gr = gw + (long long)e * DIM_;
        for (int d = lane; d < DIM_; d += 32) s += xrow[d] * gr[d];
        for (int o = 16; o; o >>= 1) s += __shfl_xor_sync(0xffffffffu, s, o);
        if (lane == 0) aff[e] = 1.f / (1.f + expf(-s)) + gb[e];
    }
    __syncthreads();
    if (tid == 0) {
        if (affOut) for (int e = 0; e < NE_; e++) affOut[(long long)bt * NE_ + e] = aff[e];
        bool used[NE_] = {};
        float wv[TOPK_]; int wi[TOPK_]; float sum = 0.f;
        for (int k = 0; k < TOPK_; k++) {
            float best = -1e30f; int bi = 0;
            for (int e = 0; e < NE_; e++)
                if (!used[e] && aff[e] > best) { best = aff[e]; bi = e; }
            used[bi] = true; wv[k] = best; wi[k] = bi; sum += best;
        }
        for (int k = 0; k < TOPK_; k++) {
            int e = wi[k];
            int pos = atomicAdd(&cnt[e], 1);
            tok[e * CAP_ + pos] = bt;
            wt [e * CAP_ + pos] = wv[k] / sum;
        }
    }
}

__global__ void silumul2_k(const float* __restrict__ a13, uint2* __restrict__ o) {
    long long i = (long long)blockIdx.x * 256 + threadIdx.x;
    if (i >= (long long)BT_ * (MOESH_/2)) return;
    long long row = i >> 10;
    int c = (int)(i & 1023) * 2;
    const float* ar = a13 + row * 4096;
    float x0 = ar[c] * ar[2048 + c];
    float x1 = ar[c + 1] * ar[2048 + c + 1];
    x0 = x0 / (1.f + expf(-x0));
    x1 = x1 / (1.f + expf(-x1));
    o[i] = split2(x0 * SC_, x1 * SC_);
}

// h12[e][ri][0:1024]=h1, [1024:2048]=h2 -> silu(h1*h2) pair-split into h1S
__global__ void silumul_routed2_k(const float* __restrict__ h12, uint2* __restrict__ o,
                                  const int* __restrict__ cnt) {
    long long i = (long long)blockIdx.x * 256 + threadIdx.x;
    if (i >= (long long)NE_ * CAP_ * (MOE_/2)) return;
    int e  = (int)(i >> 20);
    int ri = (int)((i >> 9) & (CAP_ - 1));
    if (ri >= cnt[e]) return;
    int c = (int)(i & 511) * 2;
    const float* base = h12 + ((long long)e * CAP_ + ri) * 2048;
    float x0 = base[c]     * base[1024 + c];
    float x1 = base[c + 1] * base[1024 + c + 1];
    x0 = x0 / (1.f + expf(-x0));
    x1 = x1 / (1.f + expf(-x1));
    o[i] = split2(x0 * SC_, x1 * SC_);
}

// ---------------- host helpers ------------------------------------------------
static GemmP mkP(const void* A, const void* B, void* C, int M, int N, int K,
                 int lda, int ldb, int ldc, float alpha, const float* res,
                 int zdiv, long long a1, long long a2, long long b1, long long b2,
                 long long c1, long long c2,
                 const int* Mvec, const int* aRows, const int* cRows,
                 const float* wRow, int cap, int causal, int causalAV, int outSplit) {
    GemmP p;
    p.A = A; p.B = B; p.C = C; p.res = res;
    p.M = M; p.N = N; p.K = K; p.lda = lda; p.ldb = ldb; p.ldc = ldc;
    p.alpha = alpha;
    p.aO1 = a1; p.aO2 = a2; p.bO1 = b1; p.bO2 = b2; p.cO1 = c1; p.cO2 = c2;
    p.zdiv = zdiv; p.cap = cap;
    p.Mvec = Mvec; p.aRows = aRows; p.cRows = cRows; p.wRow = wRow;
    p.causal = causal; p.causalAV = causalAV; p.outSplit = outSplit;
    return p;
}

template<int MODE>
static void gemmCA(const uint2* A, const uint2* B, void* C, int M, int N, int K,
                   int ldaP, int ldbP, int ldc, float alpha, const float* res,
                   int nz, int zdiv,
                   long long a1, long long a2, long long b1, long long b2,
                   long long c1, long long c2,
                   int causal = 0, int outSplit = 0,
                   const int* Mvec = nullptr, const int* aRows = nullptr,
                   const int* cRows = nullptr, const float* wRow = nullptr,
                   int cap = 0, int mBlocks = 0) {
    GemmP p = mkP(A, B, C, M, N, K, ldaP, ldbP, ldc, alpha, res, zdiv,
                  a1, a2, b1, b2, c1, c2,
                  Mvec, aRows, cRows, wRow, cap, causal, 0, outSplit);
    cudaFuncSetAttribute(gemm_ca<MODE>, cudaFuncAttributeMaxDynamicSharedMemorySize,
                         CA_SMEM_BYTES);
    int gy = mBlocks ? mBlocks : (M + 127) / 128;
    dim3 g((N + 127) / 128, gy, nz);
    gemm_ca<MODE><<<g, 256, CA_SMEM_BYTES>>>(p);
}

template<int MODE>
static void gemmRaw(const float* A, const float* B, void* C, int M, int N, int K,
                    int lda, int ldb, int ldc, float alpha, const float* res,
                    int nz, int zdiv,
                    long long a1, long long a2, long long b1, long long b2,
                    long long c1, long long c2,
                    const int* Mvec = nullptr, const int* aRows = nullptr,
                    const int* cRows = nullptr, const float* wRow = nullptr,
                    int cap = 0, int causalAV = 0, int outSplit = 0) {
    GemmP p = mkP(A, B, C, M, N, K, lda, ldb, ldc, alpha, res, zdiv,
                  a1, a2, b1, b2, c1, c2,
                  Mvec, aRows, cRows, wRow, cap, 0, causalAV, outSplit);
    dim3 g((N + 127) / 128, (M + 127) / 128, nz);
    gemm_k<MODE><<<g, 256>>>(p);
}

static void splitArr(const float* in, uint2* out, long long n) {
    long long n4 = n >> 2;
    split_arr_k<<<(unsigned)((n4 + 255) / 256), 256>>>((const float4*)in, out, n4);
}

extern "C" void kernel_launch(void* const* d_in, const int* in_sizes, int n_in,
                              void* d_out, int out_size) {
    const float* x      = (const float*)d_in[0];
    const float* attn_w = (const float*)d_in[3];
    const float* ffn_w  = (const float*)d_in[4];
    const float* gate_w = (const float*)d_in[5];
    const float* gate_b = (const float*)d_in[6];
    const float* w1s    = (const float*)d_in[7];
    const float* w2s    = (const float*)d_in[8];
    const float* w3s    = (const float*)d_in[9];
    const float* w1r    = (const float*)d_in[10];
    const float* w2r    = (const float*)d_in[11];
    const float* w3r    = (const float*)d_in[12];
    const float* wdkv   = (const float*)d_in[13];
    const float* wuk    = (const float*)d_in[14];
    const float* wuv    = (const float*)d_in[15];
    const float* wdq    = (const float*)d_in[16];
    const float* wuq    = (const float*)d_in[17];
    const float* wqr    = (const float*)d_in[18];
    const float* wkr    = (const float*)d_in[19];
    const float* wo     = (const float*)d_in[20];
    float* out = (float*)d_out;

    float *S, *V, *x1, *xn, *a13, *h12, *pk, *wt;
    int *cnt, *tok;
    uint2 *h2, *cdq2, *Q2, *K2, *O2, *Wo2, *xn2, *a1s, *h1S;
    uint2 *wA2, *wuk2, *wuv2, *wuq2, *wqr2, *w13s2, *w2s2, *w13r2, *w2r2;
    cudaGetSymbolAddress((void**)&S,   g_S);
    cudaGetSymbolAddress((void**)&V,   g_V);
    cudaGetSymbolAddress((void**)&x1,  g_x1);
    cudaGetSymbolAddress((void**)&xn,  g_xn);
    cudaGetSymbolAddress((void**)&a13, g_a13);
    cudaGetSymbolAddress((void**)&h12, g_h12);
    cudaGetSymbolAddress((void**)&pk,  g_pk);
    cudaGetSymbolAddress((void**)&cnt, g_cnt);
    cudaGetSymbolAddress((void**)&tok, g_tok);
    cudaGetSymbolAddress((void**)&wt,  g_wt);
    cudaGetSymbolAddress((void**)&h2,  g_h2);
    cudaGetSymbolAddress((void**)&cdq2, g_cdq2);
    cudaGetSymbolAddress((void**)&Q2,  g_Q2);
    cudaGetSymbolAddress((void**)&K2,  g_K2);
    cudaGetSymbolAddress((void**)&O2,  g_O2);
    cudaGetSymbolAddress((void**)&Wo2, g_Wo2);
    cudaGetSymbolAddress((void**)&xn2, g_xn2);
    cudaGetSymbolAddress((void**)&a1s, g_a1s);
    cudaGetSymbolAddress((void**)&h1S, g_h1S);
    cudaGetSymbolAddress((void**)&wA2,  g_wA2);
    cudaGetSymbolAddress((void**)&wuk2, g_wuk2);
    cudaGetSymbolAddress((void**)&wuv2, g_wuv2);
    cudaGetSymbolAddress((void**)&wuq2, g_wuq2);
    cudaGetSymbolAddress((void**)&wqr2, g_wqr2);
    cudaGetSymbolAddress((void**)&w13s2, g_w13s2);
    cudaGetSymbolAddress((void**)&w2s2,  g_w2s2);
    cudaGetSymbolAddress((void**)&w13r2, g_w13r2);
    cudaGetSymbolAddress((void**)&w2r2,  g_w2r2);

    // ---- weight pre-split / packing (pair format) ----
    splitArr(wdkv, wA2,                           (long long)DC_*DIM_);
    splitArr(wdq,  wA2 + (long long)DC_*DIM_/2,   (long long)DC_*DIM_);
    splitArr(wkr,  wA2 + (long long)DC_*DIM_,     (long long)DRH_*DIM_);
    splitArr(wuk,  wuk2, (long long)DH_*NH_*DC_);
    splitArr(wuv,  wuv2, (long long)DH_*NH_*DC_);
    splitArr(wuq,  wuq2, (long long)DH_*NH_*DC_);
    splitArr(wqr,  wqr2, (long long)DRH_*NH_*DC_);
    {   // shared FFN NN pair packs
        long long tot = (long long)(DIM_/2) * MOESH_;
        unsigned nb = (unsigned)((tot + 255) / 256);
        split_pack_nn_k<<<nb, 256>>>(w1s, w13s2, tot, MOESH_, 2*MOESH_, 0);
        split_pack_nn_k<<<nb, 256>>>(w3s, w13s2, tot, MOESH_, 2*MOESH_, MOESH_);
        long long tot2 = (long long)(MOESH_/2) * DIM_;
        split_pack_nn_k<<<(unsigned)((tot2 + 255)/256), 256>>>(w2s, w2s2, tot2, DIM_, DIM_, 0);
    }
    {   // routed NN pair packs
        long long totr = (long long)NE_ * (DIM_/2) * MOE_;
        unsigned nbr = (unsigned)((totr + 255) / 256);
        split_pack_nn_k<<<nbr, 256>>>(w1r, w13r2, totr, MOE_, 2*MOE_, 0);
        split_pack_nn_k<<<nbr, 256>>>(w3r, w13r2, totr, MOE_, 2*MOE_, MOE_);
        long long totr2 = (long long)NE_ * (MOE_/2) * DIM_;
        split_pack_nn_k<<<(unsigned)((totr2 + 255)/256), 256>>>(w2r, w2r2, totr2, DIM_, DIM_, 0);
    }
    pack_wo_k<<<(unsigned)(((long long)DIM_*1024 + 255)/256), 256>>>(wo, Wo2);

    // ---- attention ----
    rmsnorm_k<<<BT_, 256>>>(x, attn_w, nullptr, h2);
    gemmCA<1>(h2, wA2, pk, BT_, NCDQ_, DIM_/2, DIM_/2, DIM_/2, NCDQ_, ASC_, nullptr,
              2, 1, /*aO1=*/DIM_/4, 0, /*bO1=*/DIM_/4, 0,
              /*cO1=*/(long long)BT_*NCDQ_, 0, 0, 0);
    {
        long long np = (long long)BT_*NCDQ_/2;
        reduce_split_k<<<(unsigned)((np + 255)/256), 256>>>(pk, pk + (long long)BT_*NCDQ_, cdq2, np);
    }
    gemmCA<1>(cdq2, wuk2, K2, BT_, DH_, DC_, NCDQ_/2, NH_*DC_/2, NH_*QKD_/2, ASC_, nullptr,
              NH_, NH_, 0,0, 0, DC_/2, 0, QKD_/2, 0, 1);
    gemmCA<1>(cdq2, wuv2, (void*)V, BT_, DH_, DC_, NCDQ_/2, NH_*DC_/2, NH_*DH_, ASC_, nullptr,
              NH_, NH_, 0,0, 0, DC_/2, 0, DH_, 0, 0);
    gemmCA<1>(cdq2 + DC_/2, wuq2, Q2, BT_, DH_, DC_, NCDQ_/2, NH_*DC_/2, NH_*QKD_/2,
              ASC_, nullptr, NH_, NH_, 0,0, 0, DC_/2, 0, QKD_/2, 0, 1);
    gemmCA<1>(cdq2 + DC_/2, wqr2, Q2 + DH_/2, BT_, DRH_, DC_, NCDQ_/2, NH_*DC_/2, NH_*QKD_/2,
              ASC_, nullptr, NH_, NH_, 0,0, 0, DC_/2, 0, QKD_/2, 0, 1);
    rope_q_k<<<BT_ * NH_, 16>>>(Q2);
    rope_kr_k<<<BT_, 16>>>(cdq2, K2);
    float scale = ASC_ / sqrtf((float)QKD_);
    gemmCA<1>(Q2, K2, S, T_, T_, QKD_, NH_*QKD_/2, NH_*QKD_/2, T_, scale, nullptr,
              B_*NH_, NH_,
              (long long)T_*NH_*QKD_/2, QKD_/2,
              (long long)T_*NH_*QKD_/2, QKD_/2,
              (long long)NH_*T_*T_, (long long)T_*T_,
              /*causal=*/1, 0);
    softmax_k<<<B_ * NH_ * T_, 256>>>(S);
    gemmRaw<2>(S, V, O2, T_, DH_, T_, T_, NH_*DH_, NH_*DH_/2, ASC_, nullptr,
               B_*NH_, NH_,
               (long long)NH_*T_*T_, (long long)T_*T_,
               (long long)T_*NH_*DH_, DH_,
               (long long)T_*NH_*DH_/2, DH_/2,
               nullptr, nullptr, nullptr, nullptr, 0, /*causalAV=*/1, /*outSplit=*/1);
    gemmCA<1>(O2, Wo2, x1, BT_, DIM_, NH_*DH_, NH_*DH_/2, NH_*DH_/2, DIM_, ASC_, x,
              1, 1, 0,0,0,0,0,0, 0, 0);

    // ---- MoE ----
    rmsnorm_k<<<BT_, 256>>>(x1, ffn_w, xn, xn2);
    cudaMemsetAsync(cnt, 0, NE_ * sizeof(int));
    float* affOut = (out_size >= BT_*DIM_ + BT_*NE_) ? out + (long long)BT_*DIM_ : nullptr;
    gate_k<<<BT_, 256>>>(xn, gate_w, gate_b, affOut, cnt, tok, wt);
    gemmCA<0>(xn2, w13s2, a13, BT_, 2*MOESH_, DIM_, DIM_/2, 2*MOESH_, 2*MOESH_, ASC_, nullptr,
              1, 1, 0,0,0,0,0,0, 0, 0);
    silumul2_k<<<(unsigned)(((long long)BT_*(MOESH_/2) + 255)/256), 256>>>(a13, a1s);
    gemmCA<0>(a1s, w2s2, out, BT_, DIM_, MOESH_, MOESH_/2, DIM_, DIM_, ASC_, x1,
              1, 1, 0,0,0,0,0,0, 0, 0);
    // routed experts — CA fast path
    gemmCA<0>(xn2, w13r2, h12, CAP_, 2*MOE_, DIM_, DIM_/2, 2*MOE_, 2*MOE_, ASC_, nullptr,
              NE_, NE_, 0,0, 0, (long long)(DIM_/2)*2*MOE_, 0, (long long)CAP_*2*MOE_,
              0, 0, cnt, tok, nullptr, nullptr, CAP_, CAP_/128);
    silumul_routed2_k<<<(unsigned)(((long long)NE_*CAP_*(MOE_/2) + 255)/256), 256>>>(
        h12, h1S, cnt);
    gemmCA<0>(h1S, w2r2, out, CAP_, DIM_, MOE_, MOE_/2, DIM_, DIM_, ASC_, nullptr,
              NE_, NE_, 0, (long long)CAP_*(MOE_/2), 0, (long long)(MOE_/2)*DIM_, 0, 0,
              0, 0, cnt, nullptr, tok, wt, CAP_, CAP_/128);
}